// round 7
// baseline (speedup 1.0000x reference)
#include <cuda_runtime.h>
#include <cuda_bf16.h>
#include <cstdint>

#define NBATCH 16
#define CIN    512
#define CM     512
#define CN     128
#define HW     3136   // 56*56 = 49*64

typedef __nv_bfloat16 bf16;

// ---------------------------------------------------------------------------
// Scratch
// ---------------------------------------------------------------------------
__device__ bf16 g_wAh [CM * CIN],      g_wAl [CM * CIN];
__device__ bf16 g_wBVh[2 * CN * CIN],  g_wBVl[2 * CN * CIN];   // wB rows 0-127, wV rows 128-255
__device__ float g_bBV[2 * CN];
__device__ bf16 g_xh [NBATCH * (size_t)CIN * HW], g_xl [NBATCH * (size_t)CIN * HW];
__device__ float g_Bf[NBATCH * (size_t)CN * HW];   // pre-softmax B  [b][n][p]
__device__ float g_Vf[NBATCH * (size_t)HW * CN];   // pre-softmax V  [b][p][n]
__device__ bf16 g_aBh[NBATCH * (size_t)CN * HW],  g_aBl[NBATCH * (size_t)CN * HW];
__device__ bf16 g_aVh[NBATCH * (size_t)HW * CN],  g_aVl[NBATCH * (size_t)HW * CN];
__device__ bf16 g_xBTh[NBATCH * (size_t)CN * CIN], g_xBTl[NBATCH * (size_t)CN * CIN];
__device__ bf16 g_Gh [NBATCH * (size_t)CM * CN],  g_Gl [NBATCH * (size_t)CM * CN];

// ---------------------------------------------------------------------------
// helpers
// ---------------------------------------------------------------------------
__device__ __forceinline__ uint32_t smem_u32(const void* p) {
    uint32_t a;
    asm("{ .reg .u64 t; cvta.to.shared.u64 t, %1; cvt.u32.u64 %0, t; }"
        : "=r"(a) : "l"(p));
    return a;
}
__device__ __forceinline__ void split1(float f, uint16_t& hi, uint16_t& lo) {
    __nv_bfloat16 h = __float2bfloat16_rn(f);
    float r = f - __bfloat162float(h);
    __nv_bfloat16 l = __float2bfloat16_rn(r);
    hi = __bfloat16_as_ushort(h);
    lo = __bfloat16_as_ushort(l);
}
__device__ __forceinline__ void split2(float f0, float f1, uint32_t& hi, uint32_t& lo) {
    uint16_t h0, l0, h1, l1;
    split1(f0, h0, l0);
    split1(f1, h1, l1);
    hi = (uint32_t)h0 | ((uint32_t)h1 << 16);
    lo = (uint32_t)l0 | ((uint32_t)l1 << 16);
}

__device__ __forceinline__ void cp16(uint32_t dst, const void* src) {
    asm volatile("cp.async.cg.shared.global [%0], [%1], 16;" :: "r"(dst), "l"(src));
}
#define CP_COMMIT() asm volatile("cp.async.commit_group;")
#define CP_WAIT1()  asm volatile("cp.async.wait_group 1;")
#define CP_WAIT0()  asm volatile("cp.async.wait_group 0;")

__device__ __forceinline__ void ldsm_x4(uint32_t& r0, uint32_t& r1,
                                        uint32_t& r2, uint32_t& r3, uint32_t addr) {
    asm volatile("ldmatrix.sync.aligned.m8n8.x4.shared.b16 {%0,%1,%2,%3}, [%4];"
                 : "=r"(r0), "=r"(r1), "=r"(r2), "=r"(r3) : "r"(addr));
}
__device__ __forceinline__ void ldsm_x4t(uint32_t& r0, uint32_t& r1,
                                         uint32_t& r2, uint32_t& r3, uint32_t addr) {
    asm volatile("ldmatrix.sync.aligned.m8n8.x4.trans.shared.b16 {%0,%1,%2,%3}, [%4];"
                 : "=r"(r0), "=r"(r1), "=r"(r2), "=r"(r3) : "r"(addr));
}
__device__ __forceinline__ void mma16816(float* d, const uint32_t* a,
                                         uint32_t b0, uint32_t b1) {
    asm volatile(
        "mma.sync.aligned.m16n8k16.row.col.f32.bf16.bf16.f32 "
        "{%0,%1,%2,%3}, {%4,%5,%6,%7}, {%8,%9}, {%0,%1,%2,%3};"
        : "+f"(d[0]), "+f"(d[1]), "+f"(d[2]), "+f"(d[3])
        : "r"(a[0]), "r"(a[1]), "r"(a[2]), "r"(a[3]), "r"(b0), "r"(b1));
}

// ---------------------------------------------------------------------------
// Prep kernels
// ---------------------------------------------------------------------------
__global__ __launch_bounds__(256) void k_splitv(const float4* __restrict__ src,
                                                uint2* __restrict__ h, uint2* __restrict__ l,
                                                int n4)
{
    const int i = blockIdx.x * 256 + threadIdx.x;
    if (i < n4) {
        const float4 v = src[i];
        uint32_t h0, l0, h1, l1;
        split2(v.x, v.y, h0, l0);
        split2(v.z, v.w, h1, l1);
        h[i] = make_uint2(h0, h1);
        l[i] = make_uint2(l0, l1);
    }
}

__global__ __launch_bounds__(256) void k_biaspack(const float* __restrict__ bB,
                                                  const float* __restrict__ bV,
                                                  float* __restrict__ bBV)
{
    const int t = threadIdx.x;
    bBV[t] = (t < CN) ? bB[t] : bV[t - CN];
}

// ---------------------------------------------------------------------------
// Softmaxes -> split bf16
// ---------------------------------------------------------------------------
__global__ __launch_bounds__(256) void k_softmax_row(const float* __restrict__ in,
                                                     bf16* __restrict__ oh, bf16* __restrict__ ol)
{
    const size_t off = (size_t)blockIdx.x * HW;
    const float* __restrict__ row = in + off;
    const int t = threadIdx.x;
    __shared__ float red[256];

    float v[13];
    float m = -1e30f;
    #pragma unroll
    for (int j = 0; j < 13; ++j) {
        const int i = j * 256 + t;
        if (i < HW) { v[j] = row[i]; m = fmaxf(m, v[j]); }
        else v[j] = -1e30f;
    }
    red[t] = m; __syncthreads();
    for (int s = 128; s > 0; s >>= 1) {
        if (t < s) red[t] = fmaxf(red[t], red[t + s]);
        __syncthreads();
    }
    m = red[0]; __syncthreads();

    float sum = 0.f;
    #pragma unroll
    for (int j = 0; j < 13; ++j) {
        v[j] = __expf(v[j] - m);
        sum += v[j];
    }
    red[t] = sum; __syncthreads();
    for (int s = 128; s > 0; s >>= 1) {
        if (t < s) red[t] += red[t + s];
        __syncthreads();
    }
    const float inv = 1.0f / red[0];
    #pragma unroll
    for (int j = 0; j < 13; ++j) {
        const int i = j * 256 + t;
        if (i < HW) {
            uint16_t hh, ll;
            split1(v[j] * inv, hh, ll);
            ((uint16_t*)oh)[off + i] = hh;
            ((uint16_t*)ol)[off + i] = ll;
        }
    }
}

__global__ __launch_bounds__(256) void k_softmax128(const float* __restrict__ in,
                                                    bf16* __restrict__ oh, bf16* __restrict__ ol,
                                                    int nrows)
{
    const int row = (blockIdx.x * blockDim.x + threadIdx.x) >> 5;
    if (row >= nrows) return;
    const int lane = threadIdx.x & 31;
    const float4 v = *((const float4*)(in + (size_t)row * CN) + lane);

    float m = fmaxf(fmaxf(v.x, v.y), fmaxf(v.z, v.w));
    #pragma unroll
    for (int o = 16; o > 0; o >>= 1) m = fmaxf(m, __shfl_xor_sync(0xFFFFFFFFu, m, o));

    float ex = __expf(v.x - m), ey = __expf(v.y - m);
    float ez = __expf(v.z - m), ew = __expf(v.w - m);
    float s = ex + ey + ez + ew;
    #pragma unroll
    for (int o = 16; o > 0; o >>= 1) s += __shfl_xor_sync(0xFFFFFFFFu, s, o);

    const float inv = 1.0f / s;
    uint32_t h01, l01, h23, l23;
    split2(ex * inv, ey * inv, h01, l01);
    split2(ez * inv, ew * inv, h23, l23);
    const size_t off = (size_t)row * CN + lane * 4;
    *(uint2*)((uint16_t*)oh + off) = make_uint2(h01, h23);
    *(uint2*)((uint16_t*)ol + off) = make_uint2(l01, l23);
}

// ---------------------------------------------------------------------------
// Pipelined bf16 split-float GEMM: D[m][n] = sum_k A[m][k]*B[n][k]
//   Block tile (NMT*64) x 64, K-chunk 32, 3-stage cp.async.
//   8 warps = 4m x 2n; warp tile (NMT*16) x 32.
//   bmode 0: B K-major rows (stride ldb); bmode 1: B = Bp[k*ldb+n] (trans ldsm).
//   outmode 0: fp32 C[m*ldc+n]          1: fp32 C[n*ldc+m]
//           2: split bf16 trans          3: split bf16 normal
//           4: rows<128 -> mode0 (Cv, ldc); rows>=128 -> mode1 (C2v, ldc2)
// ---------------------------------------------------------------------------
#define APITCH 40
#define BPITCH 72
#define NSTAGE 3
#define EPITCH 68

template<int NMT>
__global__ __launch_bounds__(256, 1) void k_mma(
    const bf16* __restrict__ Ah, const bf16* __restrict__ Al,
    const bf16* __restrict__ Bh, const bf16* __restrict__ Bl,
    void* __restrict__ Cv, void* __restrict__ C2v,
    const float* __restrict__ bias,
    int Kd, int ldb, int ldc, int ldc2, int outmode, int bmode,
    long long sA, long long sB, long long sC, long long sC2)
{
    constexpr int MTILE = NMT * 64;
    constexpr int ST_AH  = 0;
    constexpr int ST_AL  = MTILE * APITCH;
    constexpr int ST_BH  = 2 * MTILE * APITCH;
    constexpr int ST_B0L = ST_BH + 64 * APITCH;
    constexpr int ST_B1L = ST_BH + 32 * BPITCH;
    constexpr int STAGE_BYTES = (2 * MTILE * APITCH + 128 * APITCH) * 2;

    extern __shared__ __align__(16) char smraw[];
    const int b = blockIdx.z;
    Ah += (size_t)b * sA; Al += (size_t)b * sA;
    Bh += (size_t)b * sB; Bl += (size_t)b * sB;
    const int m0 = blockIdx.y * MTILE;
    const int n0 = blockIdx.x * 64;
    const int tid = threadIdx.x, wid = tid >> 5, lane = tid & 31;
    const int warp_m = wid & 3, warp_n = wid >> 2;
    const uint32_t sbase = smem_u32(smraw);
    const int lrow = lane & 15, lgr = lane >> 4;

    auto load_stage = [&](int s, int k0) {
        const uint32_t base = sbase + (uint32_t)s * STAGE_BYTES;
        #pragma unroll
        for (int i = tid; i < MTILE * 4; i += 256) {
            const int r = i >> 2, c = (i & 3) << 3;
            const size_t gs = (size_t)(m0 + r) * Kd + k0 + c;
            cp16(base + (uint32_t)(ST_AH + r * APITCH + c) * 2, Ah + gs);
            cp16(base + (uint32_t)(ST_AL + r * APITCH + c) * 2, Al + gs);
        }
        if (bmode == 0) {
            const int i = tid;
            if (i < 256) {
                const int r = i >> 2, c = (i & 3) << 3;
                const size_t gs = (size_t)(n0 + r) * ldb + k0 + c;
                cp16(base + (uint32_t)(ST_BH  + r * APITCH + c) * 2, Bh + gs);
                cp16(base + (uint32_t)(ST_B0L + r * APITCH + c) * 2, Bl + gs);
            }
        } else {
            const int i = tid;
            if (i < 256) {
                const int r = i >> 3, c = (i & 7) << 3;   // 32 k-rows x 64 n
                const size_t gs = (size_t)(k0 + r) * ldb + n0 + c;
                cp16(base + (uint32_t)(ST_BH  + r * BPITCH + c) * 2, Bh + gs);
                cp16(base + (uint32_t)(ST_B1L + r * BPITCH + c) * 2, Bl + gs);
            }
        }
    };

    float acc[NMT][4][4] = {};
    const int nchunk = Kd >> 5;

    load_stage(0, 0); CP_COMMIT();
    load_stage(1, 32); CP_COMMIT();

    for (int ch = 0; ch < nchunk; ++ch) {
        CP_WAIT1();
        __syncthreads();
        if (ch + 2 < nchunk) load_stage((ch + 2) % NSTAGE, (ch + 2) << 5);
        CP_COMMIT();

        const uint32_t stb = sbase + (uint32_t)(ch % NSTAGE) * STAGE_BYTES;
        #pragma unroll
        for (int ks = 0; ks < 2; ++ks) {
            const uint32_t goff = (uint32_t)((ks * 2 + lgr) * 16);  // bytes
            uint32_t bh[4][2], bl[4][2];
            if (bmode == 0) {
                #pragma unroll
                for (int ng = 0; ng < 2; ++ng) {
                    const int row = warp_n * 32 + ng * 16 + lrow;
                    uint32_t r0, r1, r2, r3;
                    ldsm_x4(r0, r1, r2, r3, stb + (ST_BH + row * APITCH) * 2 + goff);
                    bh[ng * 2 + 0][0] = r0; bh[ng * 2 + 0][1] = r2;
                    bh[ng * 2 + 1][0] = r1; bh[ng * 2 + 1][1] = r3;
                    ldsm_x4(r0, r1, r2, r3, stb + (ST_B0L + row * APITCH) * 2 + goff);
                    bl[ng * 2 + 0][0] = r0; bl[ng * 2 + 0][1] = r2;
                    bl[ng * 2 + 1][0] = r1; bl[ng * 2 + 1][1] = r3;
                }
            } else {
                const int krow = ks * 16 + ((lane & 16) >> 1) + (lane & 7);
                #pragma unroll
                for (int ng = 0; ng < 2; ++ng) {
                    const int ncol = warp_n * 32 + ng * 16 + (lane & 8);
                    uint32_t r0, r1, r2, r3;
                    ldsm_x4t(r0, r1, r2, r3, stb + (ST_BH + krow * BPITCH + ncol) * 2);
                    bh[ng * 2 + 0][0] = r0; bh[ng * 2 + 0][1] = r2;
                    bh[ng * 2 + 1][0] = r1; bh[ng * 2 + 1][1] = r3;
                    ldsm_x4t(r0, r1, r2, r3, stb + (ST_B1L + krow * BPITCH + ncol) * 2);
                    bl[ng * 2 + 0][0] = r0; bl[ng * 2 + 0][1] = r2;
                    bl[ng * 2 + 1][0] = r1; bl[ng * 2 + 1][1] = r3;
                }
            }
            #pragma unroll
            for (int mt = 0; mt < NMT; ++mt) {
                const int row = warp_m * (16 * NMT) + mt * 16 + lrow;
                uint32_t ah[4], al[4];
                ldsm_x4(ah[0], ah[1], ah[2], ah[3],
                        stb + (ST_AH + row * APITCH) * 2 + goff);
                ldsm_x4(al[0], al[1], al[2], al[3],
                        stb + (ST_AL + row * APITCH) * 2 + goff);
                #pragma unroll
                for (int nt = 0; nt < 4; ++nt) {
                    mma16816(acc[mt][nt], ah, bh[nt][0], bh[nt][1]);
                    mma16816(acc[mt][nt], ah, bl[nt][0], bl[nt][1]);
                    mma16816(acc[mt][nt], al, bh[nt][0], bh[nt][1]);
                }
            }
        }
    }
    CP_WAIT0();
    __syncthreads();

    // ---- epilogue: stage fp32 (+bias) in SMEM, coalesced stores ----
    float* const st = (float*)smraw;   // [MTILE][EPITCH]
    {
        const int drow = lane >> 2, dcol = (lane & 3) * 2;
        #pragma unroll
        for (int mt = 0; mt < NMT; ++mt) {
            const int r0w = warp_m * (16 * NMT) + mt * 16 + drow;
            const float bv0 = bias ? bias[m0 + r0w]     : 0.0f;
            const float bv1 = bias ? bias[m0 + r0w + 8] : 0.0f;
            #pragma unroll
            for (int nt = 0; nt < 4; ++nt) {
                const int c = warp_n * 32 + nt * 8 + dcol;
                st[r0w * EPITCH + c]           = acc[mt][nt][0] + bv0;
                st[r0w * EPITCH + c + 1]       = acc[mt][nt][1] + bv0;
                st[(r0w + 8) * EPITCH + c]     = acc[mt][nt][2] + bv1;
                st[(r0w + 8) * EPITCH + c + 1] = acc[mt][nt][3] + bv1;
            }
        }
    }
    __syncthreads();

    if (outmode == 0) {
        float* C = (float*)Cv + (size_t)b * sC;
        for (int i = tid; i < MTILE * 16; i += 256) {
            const int r = i >> 4, q = (i & 15) << 2;
            float4 v = make_float4(st[r * EPITCH + q],     st[r * EPITCH + q + 1],
                                   st[r * EPITCH + q + 2], st[r * EPITCH + q + 3]);
            *(float4*)&C[(size_t)(m0 + r) * ldc + n0 + q] = v;
        }
    } else if (outmode == 1) {
        float* C = (float*)Cv + (size_t)b * sC;
        for (int i = tid; i < 64 * (MTILE / 4); i += 256) {
            const int n = i / (MTILE / 4), mq = (i % (MTILE / 4)) << 2;
            float4 v = make_float4(st[(mq + 0) * EPITCH + n], st[(mq + 1) * EPITCH + n],
                                   st[(mq + 2) * EPITCH + n], st[(mq + 3) * EPITCH + n]);
            *(float4*)&C[(size_t)(n0 + n) * ldc + m0 + mq] = v;
        }
    } else if (outmode == 2) {
        uint16_t* Ch = (uint16_t*)Cv  + (size_t)b * sC;
        uint16_t* Cl = (uint16_t*)C2v + (size_t)b * sC;
        for (int i = tid; i < 64 * (MTILE / 4); i += 256) {
            const int n = i / (MTILE / 4), mq = (i % (MTILE / 4)) << 2;
            uint32_t h0, l0, h1, l1;
            split2(st[(mq + 0) * EPITCH + n], st[(mq + 1) * EPITCH + n], h0, l0);
            split2(st[(mq + 2) * EPITCH + n], st[(mq + 3) * EPITCH + n], h1, l1);
            const size_t off = (size_t)(n0 + n) * ldc + m0 + mq;
            *(uint2*)(Ch + off) = make_uint2(h0, h1);
            *(uint2*)(Cl + off) = make_uint2(l0, l1);
        }
    } else if (outmode == 3) {
        uint16_t* Ch = (uint16_t*)Cv  + (size_t)b * sC;
        uint16_t* Cl = (uint16_t*)C2v + (size_t)b * sC;
        for (int i = tid; i < MTILE * 16; i += 256) {
            const int r = i >> 4, q = (i & 15) << 2;
            uint32_t h0, l0, h1, l1;
            split2(st[r * EPITCH + q],     st[r * EPITCH + q + 1], h0, l0);
            split2(st[r * EPITCH + q + 2], st[r * EPITCH + q + 3], h1, l1);
            const size_t off = (size_t)(m0 + r) * ldc + n0 + q;
            *(uint2*)(Ch + off) = make_uint2(h0, h1);
            *(uint2*)(Cl + off) = make_uint2(l0, l1);
        }
    } else {   // outmode 4: rows<128 -> fp32 normal into Cv; rows>=128 -> fp32 trans into C2v
        float* C  = (float*)Cv  + (size_t)b * sC;
        float* C2 = (float*)C2v + (size_t)b * sC2;
        for (int i = tid; i < 128 * 16; i += 256) {
            const int r = i >> 4, q = (i & 15) << 2;
            float4 v = make_float4(st[r * EPITCH + q],     st[r * EPITCH + q + 1],
                                   st[r * EPITCH + q + 2], st[r * EPITCH + q + 3]);
            *(float4*)&C[(size_t)r * ldc + n0 + q] = v;
        }
        for (int i = tid; i < 64 * 32; i += 256) {
            const int n = i >> 5, mq = (i & 31) << 2;
            float4 v = make_float4(st[(128 + mq + 0) * EPITCH + n],
                                   st[(128 + mq + 1) * EPITCH + n],
                                   st[(128 + mq + 2) * EPITCH + n],
                                   st[(128 + mq + 3) * EPITCH + n]);
            *(float4*)&C2[(size_t)(n0 + n) * ldc2 + mq] = v;
        }
    }
}

#define SMEM2 ((2 * 128 * APITCH + 128 * APITCH) * 2 * NSTAGE)   // 92160
#define SMEM4 ((2 * 256 * APITCH + 128 * APITCH) * 2 * NSTAGE)   // 153600

// ---------------------------------------------------------------------------
// Launch
// ---------------------------------------------------------------------------
extern "C" void kernel_launch(void* const* d_in, const int* in_sizes, int n_in,
                              void* d_out, int out_size)
{
    const float* x  = (const float*)d_in[0];
    const float* wA = (const float*)d_in[1];
    const float* bA = (const float*)d_in[2];
    const float* wB = (const float*)d_in[3];
    const float* bB = (const float*)d_in[4];
    const float* wV = (const float*)d_in[5];
    const float* bV = (const float*)d_in[6];
    float* out = (float*)d_out;

    bf16 *wAh, *wAl, *wBVh, *wBVl, *xh, *xl;
    bf16 *aBh, *aBl, *aVh, *aVl, *xBTh, *xBTl, *Gh, *Gl;
    float *Bf, *Vf, *bBV;
    cudaGetSymbolAddress((void**)&wAh,  g_wAh);  cudaGetSymbolAddress((void**)&wAl,  g_wAl);
    cudaGetSymbolAddress((void**)&wBVh, g_wBVh); cudaGetSymbolAddress((void**)&wBVl, g_wBVl);
    cudaGetSymbolAddress((void**)&bBV,  g_bBV);
    cudaGetSymbolAddress((void**)&xh,   g_xh);   cudaGetSymbolAddress((void**)&xl,   g_xl);
    cudaGetSymbolAddress((void**)&Bf,   g_Bf);   cudaGetSymbolAddress((void**)&Vf,   g_Vf);
    cudaGetSymbolAddress((void**)&aBh,  g_aBh);  cudaGetSymbolAddress((void**)&aBl,  g_aBl);
    cudaGetSymbolAddress((void**)&aVh,  g_aVh);  cudaGetSymbolAddress((void**)&aVl,  g_aVl);
    cudaGetSymbolAddress((void**)&xBTh, g_xBTh); cudaGetSymbolAddress((void**)&xBTl, g_xBTl);
    cudaGetSymbolAddress((void**)&Gh,   g_Gh);   cudaGetSymbolAddress((void**)&Gl,   g_Gl);

    cudaFuncSetAttribute(k_mma<2>, cudaFuncAttributeMaxDynamicSharedMemorySize, SMEM2);
    cudaFuncSetAttribute(k_mma<4>, cudaFuncAttributeMaxDynamicSharedMemorySize, SMEM4);

    // ---- prep (5 launches; K1 GEMM lands at ncu capture index 5) ----
    k_splitv<<<(CM * CIN / 4 + 255) / 256, 256>>>(
        (const float4*)wA, (uint2*)wAh, (uint2*)wAl, CM * CIN / 4);
    k_splitv<<<(CN * CIN / 4 + 255) / 256, 256>>>(
        (const float4*)wB, (uint2*)wBVh, (uint2*)wBVl, CN * CIN / 4);
    k_splitv<<<(CN * CIN / 4 + 255) / 256, 256>>>(
        (const float4*)wV, (uint2*)(wBVh + CN * CIN), (uint2*)(wBVl + CN * CIN), CN * CIN / 4);
    {
        const int n4 = NBATCH * CIN * HW / 4;
        k_splitv<<<(n4 + 255) / 256, 256>>>((const float4*)x, (uint2*)xh, (uint2*)xl, n4);
    }
    k_biaspack<<<1, 256>>>(bB, bV, bBV);

    // ---- K1: [Bf;Vf] = [wB;wV] @ x + bBV  (M=256 stacked, N=HW, K=512) ----
    //      rows 0-127 -> Bf normal [n][p]; rows 128-255 -> Vf trans [p][n]
    k_mma<4><<<dim3(HW / 64, 1, NBATCH), 256, SMEM4>>>(
        wBVh, wBVl, xh, xl, Bf, Vf, bBV,
        CIN, /*ldb=*/HW, /*ldc=*/HW, /*ldc2=*/CN, /*outmode=*/4, /*bmode=*/1,
        0, (long long)CIN * HW, (long long)CN * HW, (long long)HW * CN);

    // ---- softmaxes ----
    k_softmax_row<<<NBATCH * CN, 256>>>(Bf, aBh, aBl);
    {
        const int nrows  = NBATCH * HW;
        const int blocks = (nrows * 32 + 255) / 256;
        k_softmax128<<<blocks, 256>>>(Vf, aVh, aVl, nrows);
    }

    // ---- K4: xBT[n][c] = sum_p x[c][p]*attB[n][p]  -> split bf16 trans ----
    k_mma<2><<<dim3(CN / 64, CIN / 128, NBATCH), 256, SMEM2>>>(
        xh, xl, aBh, aBl, xBTh, xBTl, nullptr,
        HW, /*ldb=*/HW, /*ldc=*/CIN, 0, /*outmode=*/2, /*bmode=*/0,
        (long long)CIN * HW, (long long)CN * HW, (long long)CN * CIN, 0);

    // ---- K5: G = wA @ xB + bA  -> split bf16 normal ----
    k_mma<2><<<dim3(CN / 64, CM / 128, NBATCH), 256, SMEM2>>>(
        wAh, wAl, xBTh, xBTl, Gh, Gl, bA,
        CIN, /*ldb=*/CIN, /*ldc=*/CN, 0, /*outmode=*/3, /*bmode=*/0,
        0, (long long)CN * CIN, (long long)CM * CN, 0);

    // ---- K6: Z[m][p] = sum_n G[m][n]*attV[p][n]  -> fp32 out ----
    k_mma<4><<<dim3(HW / 64, CM / 256, NBATCH), 256, SMEM4>>>(
        Gh, Gl, aVh, aVl, out, nullptr, nullptr,
        CN, /*ldb=*/CN, /*ldc=*/HW, 0, /*outmode=*/0, /*bmode=*/0,
        (long long)CM * CN, (long long)HW * CN, (long long)CM * HW, 0);

    (void)in_sizes; (void)n_in; (void)out_size;
}

// round 8
// speedup vs baseline: 1.4952x; 1.4952x over previous
#include <cuda_runtime.h>
#include <cuda_fp16.h>
#include <cstdint>

#define NBATCH 16
#define CIN    512
#define CM     512
#define CN     128
#define HW     3136   // 56*56 = 49*64

// ---------------------------------------------------------------------------
// Scratch (fp16). A-side operands split hi/lo; B-side plain fp16.
// ---------------------------------------------------------------------------
__device__ __half g_wAh [CM * CIN],     g_wAl [CM * CIN];
__device__ __half g_wBVh[2 * CN * CIN], g_wBVl[2 * CN * CIN];  // wB 0-127 | wV 128-255
__device__ float  g_bBV[2 * CN];
__device__ __half g_xh [NBATCH * (size_t)CIN * HW], g_xl[NBATCH * (size_t)CIN * HW];
__device__ float  g_Bf[NBATCH * (size_t)CN * HW];   // pre-softmax B  [b][n][p]
__device__ float  g_Vf[NBATCH * (size_t)HW * CN];   // pre-softmax V  [b][p][n]
__device__ __half g_aB[NBATCH * (size_t)CN * HW];   // attB plain fp16 [b][n][p]
__device__ __half g_aV[NBATCH * (size_t)HW * CN];   // attV plain fp16 [b][p][n]
__device__ __half g_xBT[NBATCH * (size_t)CN * CIN]; // (x@attB^T)^T plain [b][n][c]
__device__ __half g_Gh[NBATCH * (size_t)CM * CN],  g_Gl[NBATCH * (size_t)CM * CN];

// ---------------------------------------------------------------------------
// helpers
// ---------------------------------------------------------------------------
__device__ __forceinline__ uint32_t smem_u32(const void* p) {
    uint32_t a;
    asm("{ .reg .u64 t; cvta.to.shared.u64 t, %1; cvt.u32.u64 %0, t; }"
        : "=r"(a) : "l"(p));
    return a;
}
__device__ __forceinline__ void split1h(float f, uint16_t& hi, uint16_t& lo) {
    __half h = __float2half_rn(f);
    float r = f - __half2float(h);
    __half l = __float2half_rn(r);
    hi = __half_as_ushort(h);
    lo = __half_as_ushort(l);
}
__device__ __forceinline__ void split2h(float f0, float f1, uint32_t& hi, uint32_t& lo) {
    uint16_t h0, l0, h1, l1;
    split1h(f0, h0, l0);
    split1h(f1, h1, l1);
    hi = (uint32_t)h0 | ((uint32_t)h1 << 16);
    lo = (uint32_t)l0 | ((uint32_t)l1 << 16);
}
__device__ __forceinline__ uint32_t packh2(float a, float b) {
    __half2 h = __floats2half2_rn(a, b);
    return *(uint32_t*)&h;
}

__device__ __forceinline__ void cp16(uint32_t dst, const void* src) {
    asm volatile("cp.async.cg.shared.global [%0], [%1], 16;" :: "r"(dst), "l"(src));
}
#define CP_COMMIT() asm volatile("cp.async.commit_group;")
#define CP_WAIT1()  asm volatile("cp.async.wait_group 1;")
#define CP_WAIT0()  asm volatile("cp.async.wait_group 0;")

__device__ __forceinline__ void ldsm_x4(uint32_t& r0, uint32_t& r1,
                                        uint32_t& r2, uint32_t& r3, uint32_t addr) {
    asm volatile("ldmatrix.sync.aligned.m8n8.x4.shared.b16 {%0,%1,%2,%3}, [%4];"
                 : "=r"(r0), "=r"(r1), "=r"(r2), "=r"(r3) : "r"(addr));
}
__device__ __forceinline__ void ldsm_x4t(uint32_t& r0, uint32_t& r1,
                                         uint32_t& r2, uint32_t& r3, uint32_t addr) {
    asm volatile("ldmatrix.sync.aligned.m8n8.x4.trans.shared.b16 {%0,%1,%2,%3}, [%4];"
                 : "=r"(r0), "=r"(r1), "=r"(r2), "=r"(r3) : "r"(addr));
}
__device__ __forceinline__ void mma16816h(float* d, const uint32_t* a,
                                          uint32_t b0, uint32_t b1) {
    asm volatile(
        "mma.sync.aligned.m16n8k16.row.col.f32.f16.f16.f32 "
        "{%0,%1,%2,%3}, {%4,%5,%6,%7}, {%8,%9}, {%0,%1,%2,%3};"
        : "+f"(d[0]), "+f"(d[1]), "+f"(d[2]), "+f"(d[3])
        : "r"(a[0]), "r"(a[1]), "r"(a[2]), "r"(a[3]), "r"(b0), "r"(b1));
}

// ---------------------------------------------------------------------------
// Prep kernels
// ---------------------------------------------------------------------------
__global__ __launch_bounds__(256) void k_splitv(const float4* __restrict__ src,
                                                uint2* __restrict__ h, uint2* __restrict__ l,
                                                int n4)
{
    const int i = blockIdx.x * 256 + threadIdx.x;
    if (i < n4) {
        const float4 v = src[i];
        uint32_t h0, l0, h1, l1;
        split2h(v.x, v.y, h0, l0);
        split2h(v.z, v.w, h1, l1);
        h[i] = make_uint2(h0, h1);
        l[i] = make_uint2(l0, l1);
    }
}

__global__ __launch_bounds__(256) void k_biaspack(const float* __restrict__ bB,
                                                  const float* __restrict__ bV,
                                                  float* __restrict__ bBV)
{
    const int t = threadIdx.x;
    bBV[t] = (t < CN) ? bB[t] : bV[t - CN];
}

// ---------------------------------------------------------------------------
// Softmaxes -> plain fp16
// ---------------------------------------------------------------------------
__global__ __launch_bounds__(256) void k_softmax_row(const float* __restrict__ in,
                                                     __half* __restrict__ o)
{
    const size_t off = (size_t)blockIdx.x * HW;
    const float* __restrict__ row = in + off;
    const int t = threadIdx.x;
    __shared__ float red[256];

    float v[13];
    float m = -1e30f;
    #pragma unroll
    for (int j = 0; j < 13; ++j) {
        const int i = j * 256 + t;
        if (i < HW) { v[j] = row[i]; m = fmaxf(m, v[j]); }
        else v[j] = -1e30f;
    }
    red[t] = m; __syncthreads();
    for (int s = 128; s > 0; s >>= 1) {
        if (t < s) red[t] = fmaxf(red[t], red[t + s]);
        __syncthreads();
    }
    m = red[0]; __syncthreads();

    float sum = 0.f;
    #pragma unroll
    for (int j = 0; j < 13; ++j) {
        v[j] = __expf(v[j] - m);
        sum += v[j];
    }
    red[t] = sum; __syncthreads();
    for (int s = 128; s > 0; s >>= 1) {
        if (t < s) red[t] += red[t + s];
        __syncthreads();
    }
    const float inv = 1.0f / red[0];
    #pragma unroll
    for (int j = 0; j < 13; ++j) {
        const int i = j * 256 + t;
        if (i < HW)
            ((uint16_t*)o)[off + i] = __half_as_ushort(__float2half_rn(v[j] * inv));
    }
}

__global__ __launch_bounds__(256) void k_softmax128(const float* __restrict__ in,
                                                    __half* __restrict__ o, int nrows)
{
    const int row = (blockIdx.x * blockDim.x + threadIdx.x) >> 5;
    if (row >= nrows) return;
    const int lane = threadIdx.x & 31;
    const float4 v = *((const float4*)(in + (size_t)row * CN) + lane);

    float m = fmaxf(fmaxf(v.x, v.y), fmaxf(v.z, v.w));
    #pragma unroll
    for (int of = 16; of > 0; of >>= 1) m = fmaxf(m, __shfl_xor_sync(0xFFFFFFFFu, m, of));

    float ex = __expf(v.x - m), ey = __expf(v.y - m);
    float ez = __expf(v.z - m), ew = __expf(v.w - m);
    float s = ex + ey + ez + ew;
    #pragma unroll
    for (int of = 16; of > 0; of >>= 1) s += __shfl_xor_sync(0xFFFFFFFFu, s, of);

    const float inv = 1.0f / s;
    const uint32_t h01 = packh2(ex * inv, ey * inv);
    const uint32_t h23 = packh2(ez * inv, ew * inv);
    const size_t off = (size_t)row * CN + lane * 4;
    *(uint2*)((uint16_t*)o + off) = make_uint2(h01, h23);
}

// ---------------------------------------------------------------------------
// Pipelined fp16 GEMM: D[m][n] = sum_k A[m][k]*B[n][k]
//   A = Ah + Al (fp16 split); B plain fp16. 2 MMAs per product.
//   Block tile 128x64, K-chunk 32, 3-stage cp.async, one barrier per chunk.
//   bmode 0: B K-major rows (stride ldb); bmode 1: B = Bp[k*ldb+n] (trans ldsm).
//   outmode 0: fp32 C[m*ldc+n]      1: fp32 C[n*ldc+m]
//           2: plain fp16 trans      3: split fp16 normal (Cv=hi, C2v=lo)
//           4: y==0 -> mode0 (Cv/ldc); y==1 -> mode1 (C2v/ldc2, m0out=0)
// ---------------------------------------------------------------------------
#define APITCH 40
#define BPITCH 72
#define NSTAGE 3
#define EPITCH 68
#define ST_AH  0
#define ST_AL  (128 * APITCH)            // 5120
#define ST_B   (256 * APITCH)            // 10240
#define STAGE_ELEMS (256 * APITCH + 64 * APITCH)   // 12800 halves
#define STAGE_BYTES (STAGE_ELEMS * 2)              // 25600 B
#define SMEM_BYTES (NSTAGE * STAGE_BYTES)          // 76800 B

__global__ __launch_bounds__(256) void k_mma(
    const __half* __restrict__ Ah, const __half* __restrict__ Al,
    const __half* __restrict__ Bp,
    void* __restrict__ Cv, void* __restrict__ C2v,
    const float* __restrict__ bias,
    int Kd, int ldb, int ldc, int ldc2, int outmode, int bmode,
    long long sA, long long sB, long long sC, long long sC2)
{
    extern __shared__ __align__(16) char smraw[];
    const int b = blockIdx.z;
    Ah += (size_t)b * sA; Al += (size_t)b * sA;
    Bp += (size_t)b * sB;
    const int m0 = blockIdx.y * 128;
    const int n0 = blockIdx.x * 64;
    const int tid = threadIdx.x, wid = tid >> 5, lane = tid & 31;
    const int warp_m = wid & 3, warp_n = wid >> 2;
    const uint32_t sbase = smem_u32(smraw);
    const int lrow = lane & 15, lgr = lane >> 4;

    auto load_stage = [&](int s, int k0) {
        const uint32_t base = sbase + (uint32_t)s * STAGE_BYTES;
        #pragma unroll
        for (int i = tid; i < 512; i += 256) {
            const int r = i >> 2, c = (i & 3) << 3;
            const size_t gs = (size_t)(m0 + r) * Kd + k0 + c;
            cp16(base + (uint32_t)(ST_AH + r * APITCH + c) * 2, Ah + gs);
            cp16(base + (uint32_t)(ST_AL + r * APITCH + c) * 2, Al + gs);
        }
        if (bmode == 0) {
            const int i = tid;
            if (i < 256) {
                const int r = i >> 2, c = (i & 3) << 3;
                cp16(base + (uint32_t)(ST_B + r * APITCH + c) * 2,
                     Bp + (size_t)(n0 + r) * ldb + k0 + c);
            }
        } else {
            const int i = tid;
            if (i < 256) {
                const int r = i >> 3, c = (i & 7) << 3;   // 32 k-rows x 64 n
                cp16(base + (uint32_t)(ST_B + r * BPITCH + c) * 2,
                     Bp + (size_t)(k0 + r) * ldb + n0 + c);
            }
        }
    };

    float acc[2][4][4] = {};
    const int nchunk = Kd >> 5;

    load_stage(0, 0); CP_COMMIT();
    load_stage(1, 32); CP_COMMIT();

    for (int ch = 0; ch < nchunk; ++ch) {
        CP_WAIT1();
        __syncthreads();
        if (ch + 2 < nchunk) load_stage((ch + 2) % NSTAGE, (ch + 2) << 5);
        CP_COMMIT();

        const uint32_t stb = sbase + (uint32_t)(ch % NSTAGE) * STAGE_BYTES;
        #pragma unroll
        for (int ks = 0; ks < 2; ++ks) {
            const uint32_t goff = (uint32_t)((ks * 2 + lgr) * 16);  // bytes
            uint32_t bf[4][2];
            if (bmode == 0) {
                #pragma unroll
                for (int ng = 0; ng < 2; ++ng) {
                    const int row = warp_n * 32 + ng * 16 + lrow;
                    uint32_t r0, r1, r2, r3;
                    ldsm_x4(r0, r1, r2, r3, stb + (ST_B + row * APITCH) * 2 + goff);
                    bf[ng * 2 + 0][0] = r0; bf[ng * 2 + 0][1] = r2;
                    bf[ng * 2 + 1][0] = r1; bf[ng * 2 + 1][1] = r3;
                }
            } else {
                const int krow = ks * 16 + ((lane & 16) >> 1) + (lane & 7);
                #pragma unroll
                for (int ng = 0; ng < 2; ++ng) {
                    const int ncol = warp_n * 32 + ng * 16 + (lane & 8);
                    uint32_t r0, r1, r2, r3;
                    ldsm_x4t(r0, r1, r2, r3, stb + (ST_B + krow * BPITCH + ncol) * 2);
                    bf[ng * 2 + 0][0] = r0; bf[ng * 2 + 0][1] = r2;
                    bf[ng * 2 + 1][0] = r1; bf[ng * 2 + 1][1] = r3;
                }
            }
            #pragma unroll
            for (int mt = 0; mt < 2; ++mt) {
                const int row = warp_m * 32 + mt * 16 + lrow;
                uint32_t ah[4], al[4];
                ldsm_x4(ah[0], ah[1], ah[2], ah[3],
                        stb + (ST_AH + row * APITCH) * 2 + goff);
                ldsm_x4(al[0], al[1], al[2], al[3],
                        stb + (ST_AL + row * APITCH) * 2 + goff);
                #pragma unroll
                for (int nt = 0; nt < 4; ++nt) {
                    mma16816h(acc[mt][nt], ah, bf[nt][0], bf[nt][1]);
                    mma16816h(acc[mt][nt], al, bf[nt][0], bf[nt][1]);
                }
            }
        }
    }
    CP_WAIT0();
    __syncthreads();

    // ---- effective output mode ----
    int om = outmode;
    int m0out = m0;
    if (outmode == 4) {
        if (blockIdx.y == 0) om = 0;
        else { om = 1; m0out = 0; Cv = C2v; ldc = ldc2; sC = sC2; }
    }

    // ---- epilogue: stage fp32 (+bias) in SMEM, coalesced stores ----
    float* const st = (float*)smraw;   // [128][EPITCH]
    {
        const int drow = lane >> 2, dcol = (lane & 3) * 2;
        #pragma unroll
        for (int mt = 0; mt < 2; ++mt) {
            const int r0w = warp_m * 32 + mt * 16 + drow;
            const float bv0 = bias ? bias[m0 + r0w]     : 0.0f;
            const float bv1 = bias ? bias[m0 + r0w + 8] : 0.0f;
            #pragma unroll
            for (int nt = 0; nt < 4; ++nt) {
                const int c = warp_n * 32 + nt * 8 + dcol;
                st[r0w * EPITCH + c]           = acc[mt][nt][0] + bv0;
                st[r0w * EPITCH + c + 1]       = acc[mt][nt][1] + bv0;
                st[(r0w + 8) * EPITCH + c]     = acc[mt][nt][2] + bv1;
                st[(r0w + 8) * EPITCH + c + 1] = acc[mt][nt][3] + bv1;
            }
        }
    }
    __syncthreads();

    if (om == 0) {
        float* C = (float*)Cv + (size_t)b * sC;
        for (int i = tid; i < 128 * 16; i += 256) {
            const int r = i >> 4, q = (i & 15) << 2;
            float4 v = make_float4(st[r * EPITCH + q],     st[r * EPITCH + q + 1],
                                   st[r * EPITCH + q + 2], st[r * EPITCH + q + 3]);
            *(float4*)&C[(size_t)(m0out + r) * ldc + n0 + q] = v;
        }
    } else if (om == 1) {
        float* C = (float*)Cv + (size_t)b * sC;
        for (int i = tid; i < 64 * 32; i += 256) {
            const int n = i >> 5, mq = (i & 31) << 2;
            float4 v = make_float4(st[(mq + 0) * EPITCH + n], st[(mq + 1) * EPITCH + n],
                                   st[(mq + 2) * EPITCH + n], st[(mq + 3) * EPITCH + n]);
            *(float4*)&C[(size_t)(n0 + n) * ldc + m0out + mq] = v;
        }
    } else if (om == 2) {
        uint16_t* C = (uint16_t*)Cv + (size_t)b * sC;
        for (int i = tid; i < 64 * 32; i += 256) {
            const int n = i >> 5, mq = (i & 31) << 2;
            const uint32_t h0 = packh2(st[(mq + 0) * EPITCH + n], st[(mq + 1) * EPITCH + n]);
            const uint32_t h1 = packh2(st[(mq + 2) * EPITCH + n], st[(mq + 3) * EPITCH + n]);
            *(uint2*)(C + (size_t)(n0 + n) * ldc + m0out + mq) = make_uint2(h0, h1);
        }
    } else {   // om == 3: split fp16 normal
        uint16_t* Ch = (uint16_t*)Cv  + (size_t)b * sC;
        uint16_t* Cl = (uint16_t*)C2v + (size_t)b * sC;
        for (int i = tid; i < 128 * 16; i += 256) {
            const int r = i >> 4, q = (i & 15) << 2;
            uint32_t h0, l0, h1, l1;
            split2h(st[r * EPITCH + q],     st[r * EPITCH + q + 1], h0, l0);
            split2h(st[r * EPITCH + q + 2], st[r * EPITCH + q + 3], h1, l1);
            const size_t off = (size_t)(m0out + r) * ldc + n0 + q;
            *(uint2*)(Ch + off) = make_uint2(h0, h1);
            *(uint2*)(Cl + off) = make_uint2(l0, l1);
        }
    }
}

// ---------------------------------------------------------------------------
// Launch
// ---------------------------------------------------------------------------
extern "C" void kernel_launch(void* const* d_in, const int* in_sizes, int n_in,
                              void* d_out, int out_size)
{
    const float* x  = (const float*)d_in[0];
    const float* wA = (const float*)d_in[1];
    const float* bA = (const float*)d_in[2];
    const float* wB = (const float*)d_in[3];
    const float* bB = (const float*)d_in[4];
    const float* wV = (const float*)d_in[5];
    const float* bV = (const float*)d_in[6];
    float* out = (float*)d_out;

    __half *wAh, *wAl, *wBVh, *wBVl, *xh, *xl, *aB, *aV, *xBT, *Gh, *Gl;
    float *Bf, *Vf, *bBV;
    cudaGetSymbolAddress((void**)&wAh,  g_wAh);  cudaGetSymbolAddress((void**)&wAl,  g_wAl);
    cudaGetSymbolAddress((void**)&wBVh, g_wBVh); cudaGetSymbolAddress((void**)&wBVl, g_wBVl);
    cudaGetSymbolAddress((void**)&bBV,  g_bBV);
    cudaGetSymbolAddress((void**)&xh,   g_xh);   cudaGetSymbolAddress((void**)&xl,   g_xl);
    cudaGetSymbolAddress((void**)&Bf,   g_Bf);   cudaGetSymbolAddress((void**)&Vf,   g_Vf);
    cudaGetSymbolAddress((void**)&aB,   g_aB);   cudaGetSymbolAddress((void**)&aV,   g_aV);
    cudaGetSymbolAddress((void**)&xBT,  g_xBT);
    cudaGetSymbolAddress((void**)&Gh,   g_Gh);   cudaGetSymbolAddress((void**)&Gl,   g_Gl);

    cudaFuncSetAttribute(k_mma, cudaFuncAttributeMaxDynamicSharedMemorySize, SMEM_BYTES);

    // ---- prep ----
    k_splitv<<<(CM * CIN / 4 + 255) / 256, 256>>>(
        (const float4*)wA, (uint2*)wAh, (uint2*)wAl, CM * CIN / 4);
    k_splitv<<<(CN * CIN / 4 + 255) / 256, 256>>>(
        (const float4*)wB, (uint2*)wBVh, (uint2*)wBVl, CN * CIN / 4);
    k_splitv<<<(CN * CIN / 4 + 255) / 256, 256>>>(
        (const float4*)wV, (uint2*)(wBVh + CN * CIN), (uint2*)(wBVl + CN * CIN), CN * CIN / 4);
    {
        const int n4 = NBATCH * CIN * HW / 4;
        k_splitv<<<(n4 + 255) / 256, 256>>>((const float4*)x, (uint2*)xh, (uint2*)xl, n4);
    }
    k_biaspack<<<1, 256>>>(bB, bV, bBV);

    // ---- K1: y=0 -> Bf = wB@x + bB (normal); y=1 -> Vf = wV@x + bV (trans) ----
    //      A = stacked wBV split; B = x plain fp16 (= xh) via trans-ldmatrix.
    k_mma<<<dim3(HW / 64, 2, NBATCH), 256, SMEM_BYTES>>>(
        wBVh, wBVl, xh, Bf, Vf, bBV,
        CIN, /*ldb=*/HW, /*ldc=*/HW, /*ldc2=*/CN, /*outmode=*/4, /*bmode=*/1,
        0, (long long)CIN * HW, (long long)CN * HW, (long long)HW * CN);

    // ---- softmaxes -> plain fp16 ----
    k_softmax_row<<<NBATCH * CN, 256>>>(Bf, aB);
    {
        const int nrows  = NBATCH * HW;
        const int blocks = (nrows * 32 + 255) / 256;
        k_softmax128<<<blocks, 256>>>(Vf, aV, nrows);
    }

    // ---- K4: xBT[n][c] = sum_p x[c][p]*attB[n][p] -> plain fp16 trans ----
    k_mma<<<dim3(CN / 64, CIN / 128, NBATCH), 256, SMEM_BYTES>>>(
        xh, xl, aB, xBT, nullptr, nullptr,
        HW, /*ldb=*/HW, /*ldc=*/CIN, 0, /*outmode=*/2, /*bmode=*/0,
        (long long)CIN * HW, (long long)CN * HW, (long long)CN * CIN, 0);

    // ---- K5: G = wA @ xB + bA -> split fp16 normal ----
    k_mma<<<dim3(CN / 64, CM / 128, NBATCH), 256, SMEM_BYTES>>>(
        wAh, wAl, xBT, Gh, Gl, bA,
        CIN, /*ldb=*/CIN, /*ldc=*/CN, 0, /*outmode=*/3, /*bmode=*/0,
        0, (long long)CN * CIN, (long long)CM * CN, 0);

    // ---- K6: Z[m][p] = sum_n G[m][n]*attV[p][n] -> fp32 out ----
    k_mma<<<dim3(HW / 64, CM / 128, NBATCH), 256, SMEM_BYTES>>>(
        Gh, Gl, aV, out, nullptr, nullptr,
        CN, /*ldb=*/CN, /*ldc=*/HW, 0, /*outmode=*/0, /*bmode=*/0,
        (long long)CM * CN, (long long)HW * CN, (long long)CM * HW, 0);

    (void)in_sizes; (void)n_in; (void)out_size;
}

// round 10
// speedup vs baseline: 2.0007x; 1.3381x over previous
#include <cuda_runtime.h>
#include <cuda_fp16.h>
#include <cstdint>

#define NBATCH 16
#define CIN    512
#define CM     512
#define CN     128
#define HW     3136   // 56*56 = 49*64

// ---------------------------------------------------------------------------
// Scratch (all plain fp16)
// ---------------------------------------------------------------------------
__device__ __half g_wA [CM * CIN];
__device__ __half g_wBV[2 * CN * CIN];              // wB 0-127 | wV 128-255
__device__ float  g_bBV[2 * CN];
__device__ __half g_x  [NBATCH * (size_t)CIN * HW];
__device__ float  g_Bf [NBATCH * (size_t)CN * HW];  // pre-softmax B  [b][n][p]
__device__ float  g_Vf [NBATCH * (size_t)HW * CN];  // pre-softmax V  [b][p][n]
__device__ __half g_aB [NBATCH * (size_t)CN * HW];  // attB [b][n][p]
__device__ __half g_aV [NBATCH * (size_t)HW * CN];  // attV [b][p][n]
__device__ __half g_xBT[NBATCH * (size_t)CN * CIN]; // (x@attB^T)^T [b][n][c]
__device__ __half g_G  [NBATCH * (size_t)CM * CN];  // G [b][m][n]

// ---------------------------------------------------------------------------
// helpers
// ---------------------------------------------------------------------------
__device__ __forceinline__ uint32_t smem_u32(const void* p) {
    uint32_t a;
    asm("{ .reg .u64 t; cvta.to.shared.u64 t, %1; cvt.u32.u64 %0, t; }"
        : "=r"(a) : "l"(p));
    return a;
}
__device__ __forceinline__ uint32_t packh2(float a, float b) {
    __half2 h = __floats2half2_rn(a, b);
    return *(uint32_t*)&h;
}

__device__ __forceinline__ void cp16(uint32_t dst, const void* src) {
    asm volatile("cp.async.cg.shared.global [%0], [%1], 16;" :: "r"(dst), "l"(src));
}
#define CP_COMMIT() asm volatile("cp.async.commit_group;")
#define CP_WAIT1()  asm volatile("cp.async.wait_group 1;")
#define CP_WAIT0()  asm volatile("cp.async.wait_group 0;")

__device__ __forceinline__ void ldsm_x4(uint32_t& r0, uint32_t& r1,
                                        uint32_t& r2, uint32_t& r3, uint32_t addr) {
    asm volatile("ldmatrix.sync.aligned.m8n8.x4.shared.b16 {%0,%1,%2,%3}, [%4];"
                 : "=r"(r0), "=r"(r1), "=r"(r2), "=r"(r3) : "r"(addr));
}
__device__ __forceinline__ void ldsm_x4t(uint32_t& r0, uint32_t& r1,
                                         uint32_t& r2, uint32_t& r3, uint32_t addr) {
    asm volatile("ldmatrix.sync.aligned.m8n8.x4.trans.shared.b16 {%0,%1,%2,%3}, [%4];"
                 : "=r"(r0), "=r"(r1), "=r"(r2), "=r"(r3) : "r"(addr));
}
__device__ __forceinline__ void mma16816h(float* d, const uint32_t* a,
                                          uint32_t b0, uint32_t b1) {
    asm volatile(
        "mma.sync.aligned.m16n8k16.row.col.f32.f16.f16.f32 "
        "{%0,%1,%2,%3}, {%4,%5,%6,%7}, {%8,%9}, {%0,%1,%2,%3};"
        : "+f"(d[0]), "+f"(d[1]), "+f"(d[2]), "+f"(d[3])
        : "r"(a[0]), "r"(a[1]), "r"(a[2]), "r"(a[3]), "r"(b0), "r"(b1));
}

// ---------------------------------------------------------------------------
// Prep kernels
// ---------------------------------------------------------------------------
__global__ __launch_bounds__(256) void k_cvt(const float4* __restrict__ src,
                                             uint2* __restrict__ dst, int n4)
{
    const int i = blockIdx.x * 256 + threadIdx.x;
    if (i < n4) {
        const float4 v = src[i];
        dst[i] = make_uint2(packh2(v.x, v.y), packh2(v.z, v.w));
    }
}

__global__ __launch_bounds__(256) void k_biaspack(const float* __restrict__ bB,
                                                  const float* __restrict__ bV,
                                                  float* __restrict__ bBV)
{
    const int t = threadIdx.x;
    bBV[t] = (t < CN) ? bB[t] : bV[t - CN];
}

// ---------------------------------------------------------------------------
// Softmaxes -> plain fp16
// ---------------------------------------------------------------------------
__global__ __launch_bounds__(256) void k_softmax_row(const float* __restrict__ in,
                                                     __half* __restrict__ o)
{
    const size_t off = (size_t)blockIdx.x * HW;
    const float* __restrict__ row = in + off;
    const int t = threadIdx.x;
    __shared__ float red[256];

    float v[13];
    float m = -1e30f;
    #pragma unroll
    for (int j = 0; j < 13; ++j) {
        const int i = j * 256 + t;
        if (i < HW) { v[j] = row[i]; m = fmaxf(m, v[j]); }
        else v[j] = -1e30f;
    }
    red[t] = m; __syncthreads();
    for (int s = 128; s > 0; s >>= 1) {
        if (t < s) red[t] = fmaxf(red[t], red[t + s]);
        __syncthreads();
    }
    m = red[0]; __syncthreads();

    float sum = 0.f;
    #pragma unroll
    for (int j = 0; j < 13; ++j) {
        v[j] = __expf(v[j] - m);
        sum += v[j];
    }
    red[t] = sum; __syncthreads();
    for (int s = 128; s > 0; s >>= 1) {
        if (t < s) red[t] += red[t + s];
        __syncthreads();
    }
    const float inv = 1.0f / red[0];
    #pragma unroll
    for (int j = 0; j < 13; ++j) {
        const int i = j * 256 + t;
        if (i < HW)
            ((uint16_t*)o)[off + i] = __half_as_ushort(__float2half_rn(v[j] * inv));
    }
}

__global__ __launch_bounds__(256) void k_softmax128(const float* __restrict__ in,
                                                    __half* __restrict__ o, int nrows)
{
    const int row = (blockIdx.x * blockDim.x + threadIdx.x) >> 5;
    if (row >= nrows) return;
    const int lane = threadIdx.x & 31;
    const float4 v = *((const float4*)(in + (size_t)row * CN) + lane);

    float m = fmaxf(fmaxf(v.x, v.y), fmaxf(v.z, v.w));
    #pragma unroll
    for (int of = 16; of > 0; of >>= 1) m = fmaxf(m, __shfl_xor_sync(0xFFFFFFFFu, m, of));

    float ex = __expf(v.x - m), ey = __expf(v.y - m);
    float ez = __expf(v.z - m), ew = __expf(v.w - m);
    float s = ex + ey + ez + ew;
    #pragma unroll
    for (int of = 16; of > 0; of >>= 1) s += __shfl_xor_sync(0xFFFFFFFFu, s, of);

    const float inv = 1.0f / s;
    const uint32_t h01 = packh2(ex * inv, ey * inv);
    const uint32_t h23 = packh2(ez * inv, ew * inv);
    const size_t off = (size_t)row * CN + lane * 4;
    *(uint2*)((uint16_t*)o + off) = make_uint2(h01, h23);
}

// ---------------------------------------------------------------------------
// Pipelined plain-fp16 GEMM: D[m][n] = sum_k A[m][k]*B[n][k]   (1 MMA/product)
//   Block tile 128x64, K-chunk 32, 3-stage cp.async, one barrier per chunk.
//   bmode 0: B K-major rows (stride ldb); bmode 1: B = Bp[k*ldb+n] (trans ldsm).
//   outmode 0: fp32 C[m*ldc+n]      1: fp32 C[n*ldc+m]
//           2: fp16 trans            3: fp16 normal
//           4: y==0 -> mode0 (Cv/ldc); y==1 -> mode1 (C2v/ldc2, m0out=0)
// ---------------------------------------------------------------------------
#define APITCH 40
#define BPITCH 72
#define NSTAGE 3
#define EPITCH 68
#define ST_A   0
#define ST_B   (128 * APITCH)                      // 5120
#define STAGE_ELEMS (128 * APITCH + 64 * APITCH)   // 7680 halves
#define STAGE_BYTES (STAGE_ELEMS * 2)              // 15360 B
#define SMEM_BYTES (NSTAGE * STAGE_BYTES)          // 46080 B (epilogue 34816 fits)

__global__ __launch_bounds__(256) void k_mma(
    const __half* __restrict__ Ap, const __half* __restrict__ Bp,
    void* __restrict__ Cv, void* __restrict__ C2v,
    const float* __restrict__ bias,
    int Kd, int ldb, int ldc, int ldc2, int outmode, int bmode,
    long long sA, long long sB, long long sC, long long sC2)
{
    extern __shared__ __align__(16) char smraw[];
    const int b = blockIdx.z;
    Ap += (size_t)b * sA;
    Bp += (size_t)b * sB;
    const int m0 = blockIdx.y * 128;
    const int n0 = blockIdx.x * 64;
    const int tid = threadIdx.x, wid = tid >> 5, lane = tid & 31;
    const int warp_m = wid & 3, warp_n = wid >> 2;
    const uint32_t sbase = smem_u32(smraw);
    const int lrow = lane & 15, lgr = lane >> 4;

    auto load_stage = [&](int s, int k0) {
        const uint32_t base = sbase + (uint32_t)s * STAGE_BYTES;
        #pragma unroll
        for (int i = tid; i < 512; i += 256) {
            const int r = i >> 2, c = (i & 3) << 3;
            cp16(base + (uint32_t)(ST_A + r * APITCH + c) * 2,
                 Ap + (size_t)(m0 + r) * Kd + k0 + c);
        }
        if (bmode == 0) {
            const int i = tid;
            if (i < 256) {
                const int r = i >> 2, c = (i & 3) << 3;
                cp16(base + (uint32_t)(ST_B + r * APITCH + c) * 2,
                     Bp + (size_t)(n0 + r) * ldb + k0 + c);
            }
        } else {
            const int i = tid;
            if (i < 256) {
                const int r = i >> 3, c = (i & 7) << 3;   // 32 k-rows x 64 n
                cp16(base + (uint32_t)(ST_B + r * BPITCH + c) * 2,
                     Bp + (size_t)(k0 + r) * ldb + n0 + c);
            }
        }
    };

    float acc[2][4][4] = {};
    const int nchunk = Kd >> 5;

    load_stage(0, 0); CP_COMMIT();
    load_stage(1, 32); CP_COMMIT();

    for (int ch = 0; ch < nchunk; ++ch) {
        CP_WAIT1();
        __syncthreads();
        if (ch + 2 < nchunk) load_stage((ch + 2) % NSTAGE, (ch + 2) << 5);
        CP_COMMIT();

        const uint32_t stb = sbase + (uint32_t)(ch % NSTAGE) * STAGE_BYTES;
        #pragma unroll
        for (int ks = 0; ks < 2; ++ks) {
            const uint32_t goff = (uint32_t)((ks * 2 + lgr) * 16);  // bytes
            uint32_t bf[4][2];
            if (bmode == 0) {
                #pragma unroll
                for (int ng = 0; ng < 2; ++ng) {
                    const int row = warp_n * 32 + ng * 16 + lrow;
                    uint32_t r0, r1, r2, r3;
                    ldsm_x4(r0, r1, r2, r3, stb + (ST_B + row * APITCH) * 2 + goff);
                    bf[ng * 2 + 0][0] = r0; bf[ng * 2 + 0][1] = r2;
                    bf[ng * 2 + 1][0] = r1; bf[ng * 2 + 1][1] = r3;
                }
            } else {
                const int krow = ks * 16 + ((lane & 16) >> 1) + (lane & 7);
                #pragma unroll
                for (int ng = 0; ng < 2; ++ng) {
                    const int ncol = warp_n * 32 + ng * 16 + (lane & 8);
                    uint32_t r0, r1, r2, r3;
                    ldsm_x4t(r0, r1, r2, r3, stb + (ST_B + krow * BPITCH + ncol) * 2);
                    bf[ng * 2 + 0][0] = r0; bf[ng * 2 + 0][1] = r2;
                    bf[ng * 2 + 1][0] = r1; bf[ng * 2 + 1][1] = r3;
                }
            }
            #pragma unroll
            for (int mt = 0; mt < 2; ++mt) {
                const int row = warp_m * 32 + mt * 16 + lrow;
                uint32_t af[4];
                ldsm_x4(af[0], af[1], af[2], af[3],
                        stb + (ST_A + row * APITCH) * 2 + goff);
                #pragma unroll
                for (int nt = 0; nt < 4; ++nt)
                    mma16816h(acc[mt][nt], af, bf[nt][0], bf[nt][1]);
            }
        }
    }
    CP_WAIT0();
    __syncthreads();

    // ---- effective output mode ----
    int om = outmode;
    int m0out = m0;
    if (outmode == 4) {
        if (blockIdx.y == 0) om = 0;
        else { om = 1; m0out = 0; Cv = C2v; ldc = ldc2; sC = sC2; }
    }

    // ---- epilogue: stage fp32 (+bias) in SMEM, coalesced stores ----
    float* const st = (float*)smraw;   // [128][EPITCH]
    {
        const int drow = lane >> 2, dcol = (lane & 3) * 2;
        #pragma unroll
        for (int mt = 0; mt < 2; ++mt) {
            const int r0w = warp_m * 32 + mt * 16 + drow;
            const float bv0 = bias ? bias[m0 + r0w]     : 0.0f;
            const float bv1 = bias ? bias[m0 + r0w + 8] : 0.0f;
            #pragma unroll
            for (int nt = 0; nt < 4; ++nt) {
                const int c = warp_n * 32 + nt * 8 + dcol;
                st[r0w * EPITCH + c]           = acc[mt][nt][0] + bv0;
                st[r0w * EPITCH + c + 1]       = acc[mt][nt][1] + bv0;
                st[(r0w + 8) * EPITCH + c]     = acc[mt][nt][2] + bv1;
                st[(r0w + 8) * EPITCH + c + 1] = acc[mt][nt][3] + bv1;
            }
        }
    }
    __syncthreads();

    if (om == 0) {
        float* C = (float*)Cv + (size_t)b * sC;
        for (int i = tid; i < 128 * 16; i += 256) {
            const int r = i >> 4, q = (i & 15) << 2;
            float4 v = make_float4(st[r * EPITCH + q],     st[r * EPITCH + q + 1],
                                   st[r * EPITCH + q + 2], st[r * EPITCH + q + 3]);
            *(float4*)&C[(size_t)(m0out + r) * ldc + n0 + q] = v;
        }
    } else if (om == 1) {
        float* C = (float*)Cv + (size_t)b * sC;
        for (int i = tid; i < 64 * 32; i += 256) {
            const int n = i >> 5, mq = (i & 31) << 2;
            float4 v = make_float4(st[(mq + 0) * EPITCH + n], st[(mq + 1) * EPITCH + n],
                                   st[(mq + 2) * EPITCH + n], st[(mq + 3) * EPITCH + n]);
            *(float4*)&C[(size_t)(n0 + n) * ldc + m0out + mq] = v;
        }
    } else if (om == 2) {
        uint16_t* C = (uint16_t*)Cv + (size_t)b * sC;
        for (int i = tid; i < 64 * 32; i += 256) {
            const int n = i >> 5, mq = (i & 31) << 2;
            const uint32_t h0 = packh2(st[(mq + 0) * EPITCH + n], st[(mq + 1) * EPITCH + n]);
            const uint32_t h1 = packh2(st[(mq + 2) * EPITCH + n], st[(mq + 3) * EPITCH + n]);
            *(uint2*)(C + (size_t)(n0 + n) * ldc + m0out + mq) = make_uint2(h0, h1);
        }
    } else {   // om == 3: fp16 normal
        uint16_t* C = (uint16_t*)Cv + (size_t)b * sC;
        for (int i = tid; i < 128 * 16; i += 256) {
            const int r = i >> 4, q = (i & 15) << 2;
            const uint32_t h0 = packh2(st[r * EPITCH + q],     st[r * EPITCH + q + 1]);
            const uint32_t h1 = packh2(st[r * EPITCH + q + 2], st[r * EPITCH + q + 3]);
            *(uint2*)(C + (size_t)(m0out + r) * ldc + n0 + q) = make_uint2(h0, h1);
        }
    }
}

// ---------------------------------------------------------------------------
// Launch
// ---------------------------------------------------------------------------
extern "C" void kernel_launch(void* const* d_in, const int* in_sizes, int n_in,
                              void* d_out, int out_size)
{
    const float* x  = (const float*)d_in[0];
    const float* wA = (const float*)d_in[1];
    const float* bA = (const float*)d_in[2];
    const float* wB = (const float*)d_in[3];
    const float* bB = (const float*)d_in[4];
    const float* wV = (const float*)d_in[5];
    const float* bV = (const float*)d_in[6];
    float* out = (float*)d_out;

    __half *wAp, *wBVp, *xp, *aB, *aV, *xBT, *G;
    float *Bf, *Vf, *bBV;
    cudaGetSymbolAddress((void**)&wAp,  g_wA);
    cudaGetSymbolAddress((void**)&wBVp, g_wBV);
    cudaGetSymbolAddress((void**)&bBV,  g_bBV);
    cudaGetSymbolAddress((void**)&xp,   g_x);
    cudaGetSymbolAddress((void**)&Bf,   g_Bf);  cudaGetSymbolAddress((void**)&Vf, g_Vf);
    cudaGetSymbolAddress((void**)&aB,   g_aB);  cudaGetSymbolAddress((void**)&aV, g_aV);
    cudaGetSymbolAddress((void**)&xBT,  g_xBT);
    cudaGetSymbolAddress((void**)&G,    g_G);

    cudaFuncSetAttribute(k_mma, cudaFuncAttributeMaxDynamicSharedMemorySize, SMEM_BYTES);

    // ---- prep: fp32 -> fp16 conversions ----
    k_cvt<<<(CM * CIN / 4 + 255) / 256, 256>>>((const float4*)wA, (uint2*)wAp, CM * CIN / 4);
    k_cvt<<<(CN * CIN / 4 + 255) / 256, 256>>>((const float4*)wB, (uint2*)wBVp, CN * CIN / 4);
    k_cvt<<<(CN * CIN / 4 + 255) / 256, 256>>>(
        (const float4*)wV, (uint2*)(wBVp + CN * CIN), CN * CIN / 4);
    {
        const int n4 = NBATCH * CIN * HW / 4;
        k_cvt<<<(n4 + 255) / 256, 256>>>((const float4*)x, (uint2*)xp, n4);
    }
    k_biaspack<<<1, 256>>>(bB, bV, bBV);

    // ---- K1: y=0 -> Bf = wB@x + bB (normal); y=1 -> Vf = wV@x + bV (trans) ----
    k_mma<<<dim3(HW / 64, 2, NBATCH), 256, SMEM_BYTES>>>(
        wBVp, xp, Bf, Vf, bBV,
        CIN, /*ldb=*/HW, /*ldc=*/HW, /*ldc2=*/CN, /*outmode=*/4, /*bmode=*/1,
        0, (long long)CIN * HW, (long long)CN * HW, (long long)HW * CN);

    // ---- softmaxes -> fp16 ----
    k_softmax_row<<<NBATCH * CN, 256>>>(Bf, aB);
    {
        const int nrows  = NBATCH * HW;
        const int blocks = (nrows * 32 + 255) / 256;
        k_softmax128<<<blocks, 256>>>(Vf, aV, nrows);
    }

    // ---- K4: xBT[n][c] = sum_p x[c][p]*attB[n][p] -> fp16 trans ----
    k_mma<<<dim3(CN / 64, CIN / 128, NBATCH), 256, SMEM_BYTES>>>(
        xp, aB, xBT, nullptr, nullptr,
        HW, /*ldb=*/HW, /*ldc=*/CIN, 0, /*outmode=*/2, /*bmode=*/0,
        (long long)CIN * HW, (long long)CN * HW, (long long)CN * CIN, 0);

    // ---- K5: G = wA @ xB + bA -> fp16 normal ----
    k_mma<<<dim3(CN / 64, CM / 128, NBATCH), 256, SMEM_BYTES>>>(
        wAp, xBT, G, nullptr, bA,
        CIN, /*ldb=*/CIN, /*ldc=*/CN, 0, /*outmode=*/3, /*bmode=*/0,
        0, (long long)CN * CIN, (long long)CM * CN, 0);

    // ---- K6: Z[m][p] = sum_n G[m][n]*attV[p][n] -> fp32 out ----
    k_mma<<<dim3(HW / 64, CM / 128, NBATCH), 256, SMEM_BYTES>>>(
        G, aV, out, nullptr, nullptr,
        CN, /*ldb=*/CN, /*ldc=*/HW, 0, /*outmode=*/0, /*bmode=*/0,
        (long long)CM * CN, (long long)HW * CN, (long long)CM * HW, 0);

    (void)in_sizes; (void)n_in; (void)out_size;
}

// round 11
// speedup vs baseline: 2.1318x; 1.0656x over previous
#include <cuda_runtime.h>
#include <cuda_fp16.h>
#include <cstdint>

#define NBATCH 16
#define CIN    512
#define CM     512
#define CN     128
#define HW     3136   // 56*56 = 49*64
#define KPARTS 7      // split-K factor for K4 (3136 = 7 * 448)
#define KSLICE 448

// ---------------------------------------------------------------------------
// Scratch
// ---------------------------------------------------------------------------
__device__ __half g_wA [CM * CIN];
__device__ __half g_wBV[2 * CN * CIN];              // wB 0-127 | wV 128-255
__device__ float  g_bBV[2 * CN];
__device__ __half g_x  [NBATCH * (size_t)CIN * HW];
__device__ float  g_Bf [NBATCH * (size_t)CN * HW];  // pre-softmax B  [b][n][p]
__device__ float  g_Vf [NBATCH * (size_t)HW * CN];  // pre-softmax V  [b][p][n]
__device__ __half g_aB [NBATCH * (size_t)CN * HW];  // attB [b][n][p]
__device__ __half g_aV [NBATCH * (size_t)HW * CN];  // attV [b][p][n]
__device__ float  g_P  [KPARTS * (size_t)NBATCH * CN * CIN];  // K4 partials [s][b][n][c]
__device__ __half g_xBT[NBATCH * (size_t)CN * CIN]; // (x@attB^T)^T [b][n][c]
__device__ __half g_G  [NBATCH * (size_t)CM * CN];  // G [b][m][n]

// ---------------------------------------------------------------------------
// helpers
// ---------------------------------------------------------------------------
__device__ __forceinline__ uint32_t smem_u32(const void* p) {
    uint32_t a;
    asm("{ .reg .u64 t; cvta.to.shared.u64 t, %1; cvt.u32.u64 %0, t; }"
        : "=r"(a) : "l"(p));
    return a;
}
__device__ __forceinline__ uint32_t packh2(float a, float b) {
    __half2 h = __floats2half2_rn(a, b);
    return *(uint32_t*)&h;
}

__device__ __forceinline__ void cp16(uint32_t dst, const void* src) {
    asm volatile("cp.async.cg.shared.global [%0], [%1], 16;" :: "r"(dst), "l"(src));
}
#define CP_COMMIT() asm volatile("cp.async.commit_group;")
#define CP_WAIT1()  asm volatile("cp.async.wait_group 1;")
#define CP_WAIT0()  asm volatile("cp.async.wait_group 0;")

__device__ __forceinline__ void ldsm_x4(uint32_t& r0, uint32_t& r1,
                                        uint32_t& r2, uint32_t& r3, uint32_t addr) {
    asm volatile("ldmatrix.sync.aligned.m8n8.x4.shared.b16 {%0,%1,%2,%3}, [%4];"
                 : "=r"(r0), "=r"(r1), "=r"(r2), "=r"(r3) : "r"(addr));
}
__device__ __forceinline__ void ldsm_x4t(uint32_t& r0, uint32_t& r1,
                                         uint32_t& r2, uint32_t& r3, uint32_t addr) {
    asm volatile("ldmatrix.sync.aligned.m8n8.x4.trans.shared.b16 {%0,%1,%2,%3}, [%4];"
                 : "=r"(r0), "=r"(r1), "=r"(r2), "=r"(r3) : "r"(addr));
}
__device__ __forceinline__ void mma16816h(float* d, const uint32_t* a,
                                          uint32_t b0, uint32_t b1) {
    asm volatile(
        "mma.sync.aligned.m16n8k16.row.col.f32.f16.f16.f32 "
        "{%0,%1,%2,%3}, {%4,%5,%6,%7}, {%8,%9}, {%0,%1,%2,%3};"
        : "+f"(d[0]), "+f"(d[1]), "+f"(d[2]), "+f"(d[3])
        : "r"(a[0]), "r"(a[1]), "r"(a[2]), "r"(a[3]), "r"(b0), "r"(b1));
}

// ---------------------------------------------------------------------------
// Prep kernels
// ---------------------------------------------------------------------------
__global__ __launch_bounds__(256) void k_cvt(const float4* __restrict__ src,
                                             uint2* __restrict__ dst, int n4)
{
    const int i = blockIdx.x * 256 + threadIdx.x;
    if (i < n4) {
        const float4 v = src[i];
        dst[i] = make_uint2(packh2(v.x, v.y), packh2(v.z, v.w));
    }
}

__global__ __launch_bounds__(256) void k_biaspack(const float* __restrict__ bB,
                                                  const float* __restrict__ bV,
                                                  float* __restrict__ bBV)
{
    const int t = threadIdx.x;
    bBV[t] = (t < CN) ? bB[t] : bV[t - CN];
}

// sum KPARTS fp32 partial planes -> fp16
__global__ __launch_bounds__(256) void k_red(const float4* __restrict__ P,
                                             uint2* __restrict__ out, int n4)
{
    const int i = blockIdx.x * 256 + threadIdx.x;
    if (i >= n4) return;
    float4 s = P[i];
    #pragma unroll
    for (int k = 1; k < KPARTS; ++k) {
        const float4 v = P[i + (size_t)k * n4];
        s.x += v.x; s.y += v.y; s.z += v.z; s.w += v.w;
    }
    out[i] = make_uint2(packh2(s.x, s.y), packh2(s.z, s.w));
}

// ---------------------------------------------------------------------------
// Softmaxes -> plain fp16
// ---------------------------------------------------------------------------
__global__ __launch_bounds__(256) void k_softmax_row(const float* __restrict__ in,
                                                     __half* __restrict__ o)
{
    const size_t off = (size_t)blockIdx.x * HW;
    const float* __restrict__ row = in + off;
    const int t = threadIdx.x;
    __shared__ float red[256];

    float v[13];
    float m = -1e30f;
    #pragma unroll
    for (int j = 0; j < 13; ++j) {
        const int i = j * 256 + t;
        if (i < HW) { v[j] = row[i]; m = fmaxf(m, v[j]); }
        else v[j] = -1e30f;
    }
    red[t] = m; __syncthreads();
    for (int s = 128; s > 0; s >>= 1) {
        if (t < s) red[t] = fmaxf(red[t], red[t + s]);
        __syncthreads();
    }
    m = red[0]; __syncthreads();

    float sum = 0.f;
    #pragma unroll
    for (int j = 0; j < 13; ++j) {
        v[j] = __expf(v[j] - m);
        sum += v[j];
    }
    red[t] = sum; __syncthreads();
    for (int s = 128; s > 0; s >>= 1) {
        if (t < s) red[t] += red[t + s];
        __syncthreads();
    }
    const float inv = 1.0f / red[0];
    #pragma unroll
    for (int j = 0; j < 13; ++j) {
        const int i = j * 256 + t;
        if (i < HW)
            ((uint16_t*)o)[off + i] = __half_as_ushort(__float2half_rn(v[j] * inv));
    }
}

__global__ __launch_bounds__(256) void k_softmax128(const float* __restrict__ in,
                                                    __half* __restrict__ o, int nrows)
{
    const int row = (blockIdx.x * blockDim.x + threadIdx.x) >> 5;
    if (row >= nrows) return;
    const int lane = threadIdx.x & 31;
    const float4 v = *((const float4*)(in + (size_t)row * CN) + lane);

    float m = fmaxf(fmaxf(v.x, v.y), fmaxf(v.z, v.w));
    #pragma unroll
    for (int of = 16; of > 0; of >>= 1) m = fmaxf(m, __shfl_xor_sync(0xFFFFFFFFu, m, of));

    float ex = __expf(v.x - m), ey = __expf(v.y - m);
    float ez = __expf(v.z - m), ew = __expf(v.w - m);
    float s = ex + ey + ez + ew;
    #pragma unroll
    for (int of = 16; of > 0; of >>= 1) s += __shfl_xor_sync(0xFFFFFFFFu, s, of);

    const float inv = 1.0f / s;
    const uint32_t h01 = packh2(ex * inv, ey * inv);
    const uint32_t h23 = packh2(ez * inv, ew * inv);
    const size_t off = (size_t)row * CN + lane * 4;
    *(uint2*)((uint16_t*)o + off) = make_uint2(h01, h23);
}

// ---------------------------------------------------------------------------
// Pipelined plain-fp16 GEMM: D[m][n] = sum_k A[m][k]*B[n][k]
//   Block tile 128x64, K-chunk 64, 3-stage cp.async, one barrier per chunk.
//   Split-K: kparts slices of Kslice; blockIdx.z = b*kparts + s; slice output
//            offset = s*sC2 (fp32, om=1 path).
//   bmode 0: B K-major rows (stride ldb); bmode 1: B = Bp[k*ldb+n] (trans ldsm).
//   outmode 0: fp32 C[m*ldc+n]      1: fp32 C[n*ldc+m]
//           3: fp16 normal
//           4: y==0 -> mode0 (Cv/ldc); y==1 -> mode1 (C2v/ldc2, m0out=0)
// ---------------------------------------------------------------------------
#define TPITCH 72                                  // halves per row (144B) - conflict-free
#define NSTAGE 3
#define EPITCH 68
#define ST_A   0
#define ST_B   (128 * TPITCH)                      // 9216
#define STAGE_ELEMS (128 * TPITCH + 64 * TPITCH)   // 13824 halves
#define STAGE_BYTES (STAGE_ELEMS * 2)              // 27648 B
#define SMEM_BYTES (NSTAGE * STAGE_BYTES)          // 82944 B

__global__ __launch_bounds__(256) void k_mma(
    const __half* __restrict__ Ap, const __half* __restrict__ Bp,
    void* __restrict__ Cv, void* __restrict__ C2v,
    const float* __restrict__ bias,
    int Kd, int ldb, int ldc, int ldc2, int outmode, int bmode,
    int kparts, int Kslice,
    long long sA, long long sB, long long sC, long long sC2)
{
    extern __shared__ __align__(16) char smraw[];
    const int b = blockIdx.z / kparts;
    const int ks_id = blockIdx.z - b * kparts;
    const int koff = ks_id * Kslice;
    Ap += (size_t)b * sA;
    Bp += (size_t)b * sB;
    const int m0 = blockIdx.y * 128;
    const int n0 = blockIdx.x * 64;
    const int tid = threadIdx.x, wid = tid >> 5, lane = tid & 31;
    const int warp_m = wid & 3, warp_n = wid >> 2;
    const uint32_t sbase = smem_u32(smraw);
    const int lrow = lane & 15, lgr = lane >> 4;

    auto load_stage = [&](int s, int k0) {
        const uint32_t base = sbase + (uint32_t)s * STAGE_BYTES;
        #pragma unroll
        for (int i = tid; i < 1024; i += 256) {
            const int r = i >> 3, c = (i & 7) << 3;
            cp16(base + (uint32_t)(ST_A + r * TPITCH + c) * 2,
                 Ap + (size_t)(m0 + r) * Kd + k0 + c);
        }
        if (bmode == 0) {
            #pragma unroll
            for (int i = tid; i < 512; i += 256) {
                const int r = i >> 3, c = (i & 7) << 3;
                cp16(base + (uint32_t)(ST_B + r * TPITCH + c) * 2,
                     Bp + (size_t)(n0 + r) * ldb + k0 + c);
            }
        } else {
            #pragma unroll
            for (int i = tid; i < 512; i += 256) {
                const int r = i >> 3, c = (i & 7) << 3;   // 64 k-rows x 64 n
                cp16(base + (uint32_t)(ST_B + r * TPITCH + c) * 2,
                     Bp + (size_t)(k0 + r) * ldb + n0 + c);
            }
        }
    };

    float acc[2][4][4] = {};
    const int nchunk = Kslice >> 6;

    load_stage(0, koff); CP_COMMIT();
    load_stage(1, koff + 64); CP_COMMIT();

    for (int ch = 0; ch < nchunk; ++ch) {
        CP_WAIT1();
        __syncthreads();
        if (ch + 2 < nchunk) load_stage((ch + 2) % NSTAGE, koff + ((ch + 2) << 6));
        CP_COMMIT();

        const uint32_t stb = sbase + (uint32_t)(ch % NSTAGE) * STAGE_BYTES;
        #pragma unroll
        for (int ks = 0; ks < 4; ++ks) {
            const uint32_t goff = (uint32_t)((ks * 2 + lgr) * 16);  // bytes, 0..112
            uint32_t bf[4][2];
            if (bmode == 0) {
                #pragma unroll
                for (int ng = 0; ng < 2; ++ng) {
                    const int row = warp_n * 32 + ng * 16 + lrow;
                    uint32_t r0, r1, r2, r3;
                    ldsm_x4(r0, r1, r2, r3, stb + (ST_B + row * TPITCH) * 2 + goff);
                    bf[ng * 2 + 0][0] = r0; bf[ng * 2 + 0][1] = r2;
                    bf[ng * 2 + 1][0] = r1; bf[ng * 2 + 1][1] = r3;
                }
            } else {
                const int krow = ks * 16 + ((lane & 16) >> 1) + (lane & 7);
                #pragma unroll
                for (int ng = 0; ng < 2; ++ng) {
                    const int ncol = warp_n * 32 + ng * 16 + (lane & 8);
                    uint32_t r0, r1, r2, r3;
                    ldsm_x4t(r0, r1, r2, r3, stb + (ST_B + krow * TPITCH + ncol) * 2);
                    bf[ng * 2 + 0][0] = r0; bf[ng * 2 + 0][1] = r2;
                    bf[ng * 2 + 1][0] = r1; bf[ng * 2 + 1][1] = r3;
                }
            }
            #pragma unroll
            for (int mt = 0; mt < 2; ++mt) {
                const int row = warp_m * 32 + mt * 16 + lrow;
                uint32_t af[4];
                ldsm_x4(af[0], af[1], af[2], af[3],
                        stb + (ST_A + row * TPITCH) * 2 + goff);
                #pragma unroll
                for (int nt = 0; nt < 4; ++nt)
                    mma16816h(acc[mt][nt], af, bf[nt][0], bf[nt][1]);
            }
        }
    }
    CP_WAIT0();
    __syncthreads();

    // ---- effective output mode ----
    int om = outmode;
    int m0out = m0;
    if (outmode == 4) {
        if (blockIdx.y == 0) om = 0;
        else { om = 1; m0out = 0; Cv = C2v; ldc = ldc2; sC = sC2; }
    } else if (kparts > 1) {
        Cv = (void*)((float*)Cv + (size_t)ks_id * sC2);   // slice offset
    }

    // ---- epilogue: stage fp32 (+bias) in SMEM, coalesced stores ----
    float* const st = (float*)smraw;   // [128][EPITCH]
    {
        const int drow = lane >> 2, dcol = (lane & 3) * 2;
        #pragma unroll
        for (int mt = 0; mt < 2; ++mt) {
            const int r0w = warp_m * 32 + mt * 16 + drow;
            const float bv0 = bias ? bias[m0 + r0w]     : 0.0f;
            const float bv1 = bias ? bias[m0 + r0w + 8] : 0.0f;
            #pragma unroll
            for (int nt = 0; nt < 4; ++nt) {
                const int c = warp_n * 32 + nt * 8 + dcol;
                st[r0w * EPITCH + c]           = acc[mt][nt][0] + bv0;
                st[r0w * EPITCH + c + 1]       = acc[mt][nt][1] + bv0;
                st[(r0w + 8) * EPITCH + c]     = acc[mt][nt][2] + bv1;
                st[(r0w + 8) * EPITCH + c + 1] = acc[mt][nt][3] + bv1;
            }
        }
    }
    __syncthreads();

    if (om == 0) {
        float* C = (float*)Cv + (size_t)b * sC;
        for (int i = tid; i < 128 * 16; i += 256) {
            const int r = i >> 4, q = (i & 15) << 2;
            float4 v = make_float4(st[r * EPITCH + q],     st[r * EPITCH + q + 1],
                                   st[r * EPITCH + q + 2], st[r * EPITCH + q + 3]);
            *(float4*)&C[(size_t)(m0out + r) * ldc + n0 + q] = v;
        }
    } else if (om == 1) {
        float* C = (float*)Cv + (size_t)b * sC;
        for (int i = tid; i < 64 * 32; i += 256) {
            const int n = i >> 5, mq = (i & 31) << 2;
            float4 v = make_float4(st[(mq + 0) * EPITCH + n], st[(mq + 1) * EPITCH + n],
                                   st[(mq + 2) * EPITCH + n], st[(mq + 3) * EPITCH + n]);
            *(float4*)&C[(size_t)(n0 + n) * ldc + m0out + mq] = v;
        }
    } else {   // om == 3: fp16 normal
        uint16_t* C = (uint16_t*)Cv + (size_t)b * sC;
        for (int i = tid; i < 128 * 16; i += 256) {
            const int r = i >> 4, q = (i & 15) << 2;
            const uint32_t h0 = packh2(st[r * EPITCH + q],     st[r * EPITCH + q + 1]);
            const uint32_t h1 = packh2(st[r * EPITCH + q + 2], st[r * EPITCH + q + 3]);
            *(uint2*)(C + (size_t)(m0out + r) * ldc + n0 + q) = make_uint2(h0, h1);
        }
    }
}

// ---------------------------------------------------------------------------
// Launch
// ---------------------------------------------------------------------------
extern "C" void kernel_launch(void* const* d_in, const int* in_sizes, int n_in,
                              void* d_out, int out_size)
{
    const float* x  = (const float*)d_in[0];
    const float* wA = (const float*)d_in[1];
    const float* bA = (const float*)d_in[2];
    const float* wB = (const float*)d_in[3];
    const float* bB = (const float*)d_in[4];
    const float* wV = (const float*)d_in[5];
    const float* bV = (const float*)d_in[6];
    float* out = (float*)d_out;

    __half *wAp, *wBVp, *xp, *aB, *aV, *xBT, *G;
    float *Bf, *Vf, *bBV, *P;
    cudaGetSymbolAddress((void**)&wAp,  g_wA);
    cudaGetSymbolAddress((void**)&wBVp, g_wBV);
    cudaGetSymbolAddress((void**)&bBV,  g_bBV);
    cudaGetSymbolAddress((void**)&xp,   g_x);
    cudaGetSymbolAddress((void**)&Bf,   g_Bf);  cudaGetSymbolAddress((void**)&Vf, g_Vf);
    cudaGetSymbolAddress((void**)&aB,   g_aB);  cudaGetSymbolAddress((void**)&aV, g_aV);
    cudaGetSymbolAddress((void**)&P,    g_P);
    cudaGetSymbolAddress((void**)&xBT,  g_xBT);
    cudaGetSymbolAddress((void**)&G,    g_G);

    cudaFuncSetAttribute(k_mma, cudaFuncAttributeMaxDynamicSharedMemorySize, SMEM_BYTES);

    // ---- prep: fp32 -> fp16 conversions ----
    k_cvt<<<(CM * CIN / 4 + 255) / 256, 256>>>((const float4*)wA, (uint2*)wAp, CM * CIN / 4);
    k_cvt<<<(CN * CIN / 4 + 255) / 256, 256>>>((const float4*)wB, (uint2*)wBVp, CN * CIN / 4);
    k_cvt<<<(CN * CIN / 4 + 255) / 256, 256>>>(
        (const float4*)wV, (uint2*)(wBVp + CN * CIN), CN * CIN / 4);
    {
        const int n4 = NBATCH * CIN * HW / 4;
        k_cvt<<<(n4 + 255) / 256, 256>>>((const float4*)x, (uint2*)xp, n4);
    }
    k_biaspack<<<1, 256>>>(bB, bV, bBV);

    // ---- K1: y=0 -> Bf = wB@x + bB (normal); y=1 -> Vf = wV@x + bV (trans) ----
    k_mma<<<dim3(HW / 64, 2, NBATCH), 256, SMEM_BYTES>>>(
        wBVp, xp, Bf, Vf, bBV,
        CIN, /*ldb=*/HW, /*ldc=*/HW, /*ldc2=*/CN, /*outmode=*/4, /*bmode=*/1,
        1, CIN,
        0, (long long)CIN * HW, (long long)CN * HW, (long long)HW * CN);

    // ---- softmaxes -> fp16 ----
    k_softmax_row<<<NBATCH * CN, 256>>>(Bf, aB);
    {
        const int nrows  = NBATCH * HW;
        const int blocks = (nrows * 32 + 255) / 256;
        k_softmax128<<<blocks, 256>>>(Vf, aV, nrows);
    }

    // ---- K4 (split-K x7): P[s] += x@attB^T slices -> fp32 trans partials ----
    k_mma<<<dim3(CN / 64, CIN / 128, NBATCH * KPARTS), 256, SMEM_BYTES>>>(
        xp, aB, P, nullptr, nullptr,
        HW, /*ldb=*/HW, /*ldc=*/CIN, 0, /*outmode=*/1, /*bmode=*/0,
        KPARTS, KSLICE,
        (long long)CIN * HW, (long long)CN * HW,
        (long long)CN * CIN, (long long)NBATCH * CN * CIN);

    // ---- reduce partials -> fp16 xBT ----
    {
        const int n4 = NBATCH * CN * CIN / 4;
        k_red<<<(n4 + 255) / 256, 256>>>((const float4*)P, (uint2*)xBT, n4);
    }

    // ---- K5: G = wA @ xB + bA -> fp16 normal ----
    k_mma<<<dim3(CN / 64, CM / 128, NBATCH), 256, SMEM_BYTES>>>(
        wAp, xBT, G, nullptr, bA,
        CIN, /*ldb=*/CIN, /*ldc=*/CN, 0, /*outmode=*/3, /*bmode=*/0,
        1, CIN,
        0, (long long)CN * CIN, (long long)CM * CN, 0);

    // ---- K6: Z[m][p] = sum_n G[m][n]*attV[p][n] -> fp32 out ----
    k_mma<<<dim3(HW / 64, CM / 128, NBATCH), 256, SMEM_BYTES>>>(
        G, aV, out, nullptr, nullptr,
        CN, /*ldb=*/CN, /*ldc=*/HW, 0, /*outmode=*/0, /*bmode=*/0,
        1, CN,
        (long long)CM * CN, (long long)HW * CN, (long long)CM * HW, 0);

    (void)in_sizes; (void)n_in; (void)out_size;
}

// round 12
// speedup vs baseline: 2.2865x; 1.0726x over previous
#include <cuda_runtime.h>
#include <cuda_fp16.h>
#include <cstdint>

#define NBATCH 16
#define CIN    512
#define CM     512
#define CN     128
#define HW     3136   // 56*56 = 49*64
#define KPARTS 7      // split-K factor for K4 (3136 = 7 * 448)
#define KSLICE 448

// ---------------------------------------------------------------------------
// Scratch
// ---------------------------------------------------------------------------
__device__ __half g_wA [CM * CIN];
__device__ __half g_wBV[2 * CN * CIN];              // wB 0-127 | wV 128-255
__device__ float  g_bBV[2 * CN];
__device__ __half g_x  [NBATCH * (size_t)CIN * HW];
__device__ float  g_Bf [NBATCH * (size_t)CN * HW];  // pre-softmax B  [b][n][p]
__device__ __half g_aB [NBATCH * (size_t)CN * HW];  // attB [b][n][p]
__device__ __half g_aV [NBATCH * (size_t)HW * CN];  // attV [b][p][n]
__device__ float  g_P  [KPARTS * (size_t)NBATCH * CN * CIN];  // K4 partials
__device__ __half g_xBT[NBATCH * (size_t)CN * CIN]; // (x@attB^T)^T [b][n][c]
__device__ __half g_G  [NBATCH * (size_t)CM * CN];  // G [b][m][n]

// ---------------------------------------------------------------------------
// helpers
// ---------------------------------------------------------------------------
__device__ __forceinline__ uint32_t smem_u32(const void* p) {
    uint32_t a;
    asm("{ .reg .u64 t; cvta.to.shared.u64 t, %1; cvt.u32.u64 %0, t; }"
        : "=r"(a) : "l"(p));
    return a;
}
__device__ __forceinline__ uint32_t packh2(float a, float b) {
    __half2 h = __floats2half2_rn(a, b);
    return *(uint32_t*)&h;
}

__device__ __forceinline__ void cp16(uint32_t dst, const void* src) {
    asm volatile("cp.async.cg.shared.global [%0], [%1], 16;" :: "r"(dst), "l"(src));
}
#define CP_COMMIT() asm volatile("cp.async.commit_group;")
#define CP_WAIT1()  asm volatile("cp.async.wait_group 1;")
#define CP_WAIT0()  asm volatile("cp.async.wait_group 0;")

__device__ __forceinline__ void ldsm_x4(uint32_t& r0, uint32_t& r1,
                                        uint32_t& r2, uint32_t& r3, uint32_t addr) {
    asm volatile("ldmatrix.sync.aligned.m8n8.x4.shared.b16 {%0,%1,%2,%3}, [%4];"
                 : "=r"(r0), "=r"(r1), "=r"(r2), "=r"(r3) : "r"(addr));
}
__device__ __forceinline__ void ldsm_x4t(uint32_t& r0, uint32_t& r1,
                                         uint32_t& r2, uint32_t& r3, uint32_t addr) {
    asm volatile("ldmatrix.sync.aligned.m8n8.x4.trans.shared.b16 {%0,%1,%2,%3}, [%4];"
                 : "=r"(r0), "=r"(r1), "=r"(r2), "=r"(r3) : "r"(addr));
}
__device__ __forceinline__ void mma16816h(float* d, const uint32_t* a,
                                          uint32_t b0, uint32_t b1) {
    asm volatile(
        "mma.sync.aligned.m16n8k16.row.col.f32.f16.f16.f32 "
        "{%0,%1,%2,%3}, {%4,%5,%6,%7}, {%8,%9}, {%0,%1,%2,%3};"
        : "+f"(d[0]), "+f"(d[1]), "+f"(d[2]), "+f"(d[3])
        : "r"(a[0]), "r"(a[1]), "r"(a[2]), "r"(a[3]), "r"(b0), "r"(b1));
}

// ---------------------------------------------------------------------------
// Prep: all three weight conversions + bias pack in ONE launch.
//   i in [0, 65536)        -> wA  (float4 -> uint2)
//   i in [65536, 81920)    -> wB  -> wBV[0:]
//   i in [81920, 98304)    -> wV  -> wBV[16384:]
//   i < 256                -> also pack biases
// ---------------------------------------------------------------------------
__global__ __launch_bounds__(256) void k_prep(
    const float4* __restrict__ wA4, const float4* __restrict__ wB4,
    const float4* __restrict__ wV4,
    const float* __restrict__ bB, const float* __restrict__ bV,
    uint2* __restrict__ wAp, uint2* __restrict__ wBVp, float* __restrict__ bBV)
{
    const int i = blockIdx.x * 256 + threadIdx.x;
    float4 v;
    uint2* dst = nullptr;
    if (i < 65536)       { v = wA4[i];          dst = wAp + i; }
    else if (i < 81920)  { v = wB4[i - 65536];  dst = wBVp + (i - 65536); }
    else if (i < 98304)  { v = wV4[i - 81920];  dst = wBVp + 16384 + (i - 81920); }
    if (dst) *dst = make_uint2(packh2(v.x, v.y), packh2(v.z, v.w));
    if (i < 256) bBV[i] = (i < CN) ? bB[i] : bV[i - CN];
}

__global__ __launch_bounds__(256) void k_cvt(const float4* __restrict__ src,
                                             uint2* __restrict__ dst, int n4)
{
    const int i = blockIdx.x * 256 + threadIdx.x;
    if (i < n4) {
        const float4 v = src[i];
        dst[i] = make_uint2(packh2(v.x, v.y), packh2(v.z, v.w));
    }
}

// sum KPARTS fp32 partial planes -> fp16
__global__ __launch_bounds__(256) void k_red(const float4* __restrict__ P,
                                             uint2* __restrict__ out, int n4)
{
    const int i = blockIdx.x * 256 + threadIdx.x;
    if (i >= n4) return;
    float4 s = P[i];
    #pragma unroll
    for (int k = 1; k < KPARTS; ++k) {
        const float4 v = P[i + (size_t)k * n4];
        s.x += v.x; s.y += v.y; s.z += v.z; s.w += v.w;
    }
    out[i] = make_uint2(packh2(s.x, s.y), packh2(s.z, s.w));
}

// ---------------------------------------------------------------------------
// Row softmax (attB) -> fp16
// ---------------------------------------------------------------------------
__global__ __launch_bounds__(256) void k_softmax_row(const float* __restrict__ in,
                                                     __half* __restrict__ o)
{
    const size_t off = (size_t)blockIdx.x * HW;
    const float* __restrict__ row = in + off;
    const int t = threadIdx.x;
    __shared__ float red[256];

    float v[13];
    float m = -1e30f;
    #pragma unroll
    for (int j = 0; j < 13; ++j) {
        const int i = j * 256 + t;
        if (i < HW) { v[j] = row[i]; m = fmaxf(m, v[j]); }
        else v[j] = -1e30f;
    }
    red[t] = m; __syncthreads();
    for (int s = 128; s > 0; s >>= 1) {
        if (t < s) red[t] = fmaxf(red[t], red[t + s]);
        __syncthreads();
    }
    m = red[0]; __syncthreads();

    float sum = 0.f;
    #pragma unroll
    for (int j = 0; j < 13; ++j) {
        v[j] = __expf(v[j] - m);
        sum += v[j];
    }
    red[t] = sum; __syncthreads();
    for (int s = 128; s > 0; s >>= 1) {
        if (t < s) red[t] += red[t + s];
        __syncthreads();
    }
    const float inv = 1.0f / red[0];
    #pragma unroll
    for (int j = 0; j < 13; ++j) {
        const int i = j * 256 + t;
        if (i < HW)
            ((uint16_t*)o)[off + i] = __half_as_ushort(__float2half_rn(v[j] * inv));
    }
}

// ---------------------------------------------------------------------------
// Pipelined plain-fp16 GEMM: D[m][n] = sum_k A[m][k]*B[n][k]
//   Block tile 128x64, K-chunk 64, 3-stage cp.async.
//   bmode 0: B K-major (stride ldb); bmode 1: B = Bp[k*ldb+n] (trans ldsm).
//   outmode 0: fp32 C[m*ldc+n]   1: fp32 C[n*ldc+m]   3: fp16 normal
//           4: y==0 -> mode0 (Bf); y==1 -> FUSED channel softmax -> fp16 C2v
//              (rows of tile = all CN channels; per-pixel softmax in SMEM)
// ---------------------------------------------------------------------------
#define TPITCH 72
#define NSTAGE 3
#define EPITCH 68
#define ST_A   0
#define ST_B   (128 * TPITCH)
#define STAGE_ELEMS (128 * TPITCH + 64 * TPITCH)
#define STAGE_BYTES (STAGE_ELEMS * 2)              // 27648 B
#define SMEM_BYTES (NSTAGE * STAGE_BYTES)          // 82944 B

__global__ __launch_bounds__(256) void k_mma(
    const __half* __restrict__ Ap, const __half* __restrict__ Bp,
    void* __restrict__ Cv, void* __restrict__ C2v,
    const float* __restrict__ bias,
    int Kd, int ldb, int ldc, int ldc2, int outmode, int bmode,
    int kparts, int Kslice,
    long long sA, long long sB, long long sC, long long sC2)
{
    extern __shared__ __align__(16) char smraw[];
    const int b = blockIdx.z / kparts;
    const int ks_id = blockIdx.z - b * kparts;
    const int koff = ks_id * Kslice;
    Ap += (size_t)b * sA;
    Bp += (size_t)b * sB;
    const int m0 = blockIdx.y * 128;
    const int n0 = blockIdx.x * 64;
    const int tid = threadIdx.x, wid = tid >> 5, lane = tid & 31;
    const int warp_m = wid & 3, warp_n = wid >> 2;
    const uint32_t sbase = smem_u32(smraw);
    const int lrow = lane & 15, lgr = lane >> 4;

    auto load_stage = [&](int s, int k0) {
        const uint32_t base = sbase + (uint32_t)s * STAGE_BYTES;
        #pragma unroll
        for (int i = tid; i < 1024; i += 256) {
            const int r = i >> 3, c = (i & 7) << 3;
            cp16(base + (uint32_t)(ST_A + r * TPITCH + c) * 2,
                 Ap + (size_t)(m0 + r) * Kd + k0 + c);
        }
        if (bmode == 0) {
            #pragma unroll
            for (int i = tid; i < 512; i += 256) {
                const int r = i >> 3, c = (i & 7) << 3;
                cp16(base + (uint32_t)(ST_B + r * TPITCH + c) * 2,
                     Bp + (size_t)(n0 + r) * ldb + k0 + c);
            }
        } else {
            #pragma unroll
            for (int i = tid; i < 512; i += 256) {
                const int r = i >> 3, c = (i & 7) << 3;   // 64 k-rows x 64 n
                cp16(base + (uint32_t)(ST_B + r * TPITCH + c) * 2,
                     Bp + (size_t)(k0 + r) * ldb + n0 + c);
            }
        }
    };

    float acc[2][4][4] = {};
    const int nchunk = Kslice >> 6;

    load_stage(0, koff); CP_COMMIT();
    load_stage(1, koff + 64); CP_COMMIT();

    for (int ch = 0; ch < nchunk; ++ch) {
        CP_WAIT1();
        __syncthreads();
        if (ch + 2 < nchunk) load_stage((ch + 2) % NSTAGE, koff + ((ch + 2) << 6));
        CP_COMMIT();

        const uint32_t stb = sbase + (uint32_t)(ch % NSTAGE) * STAGE_BYTES;
        #pragma unroll
        for (int ks = 0; ks < 4; ++ks) {
            const uint32_t goff = (uint32_t)((ks * 2 + lgr) * 16);
            uint32_t bf[4][2];
            if (bmode == 0) {
                #pragma unroll
                for (int ng = 0; ng < 2; ++ng) {
                    const int row = warp_n * 32 + ng * 16 + lrow;
                    uint32_t r0, r1, r2, r3;
                    ldsm_x4(r0, r1, r2, r3, stb + (ST_B + row * TPITCH) * 2 + goff);
                    bf[ng * 2 + 0][0] = r0; bf[ng * 2 + 0][1] = r2;
                    bf[ng * 2 + 1][0] = r1; bf[ng * 2 + 1][1] = r3;
                }
            } else {
                const int krow = ks * 16 + ((lane & 16) >> 1) + (lane & 7);
                #pragma unroll
                for (int ng = 0; ng < 2; ++ng) {
                    const int ncol = warp_n * 32 + ng * 16 + (lane & 8);
                    uint32_t r0, r1, r2, r3;
                    ldsm_x4t(r0, r1, r2, r3, stb + (ST_B + krow * TPITCH + ncol) * 2);
                    bf[ng * 2 + 0][0] = r0; bf[ng * 2 + 0][1] = r2;
                    bf[ng * 2 + 1][0] = r1; bf[ng * 2 + 1][1] = r3;
                }
            }
            #pragma unroll
            for (int mt = 0; mt < 2; ++mt) {
                const int row = warp_m * 32 + mt * 16 + lrow;
                uint32_t af[4];
                ldsm_x4(af[0], af[1], af[2], af[3],
                        stb + (ST_A + row * TPITCH) * 2 + goff);
                #pragma unroll
                for (int nt = 0; nt < 4; ++nt)
                    mma16816h(acc[mt][nt], af, bf[nt][0], bf[nt][1]);
            }
        }
    }
    CP_WAIT0();
    __syncthreads();

    // ---- effective output mode ----
    int om = outmode;
    int m0out = m0;
    if (outmode == 4) {
        om = (blockIdx.y == 0) ? 0 : 5;     // 5 = fused channel softmax -> C2v
    } else if (kparts > 1) {
        Cv = (void*)((float*)Cv + (size_t)ks_id * sC2);
    }

    // ---- stage fp32 (+bias) in SMEM ----
    float* const st = (float*)smraw;   // [128][EPITCH]
    {
        const int drow = lane >> 2, dcol = (lane & 3) * 2;
        #pragma unroll
        for (int mt = 0; mt < 2; ++mt) {
            const int r0w = warp_m * 32 + mt * 16 + drow;
            const float bv0 = bias ? bias[m0 + r0w]     : 0.0f;
            const float bv1 = bias ? bias[m0 + r0w + 8] : 0.0f;
            #pragma unroll
            for (int nt = 0; nt < 4; ++nt) {
                const int c = warp_n * 32 + nt * 8 + dcol;
                st[r0w * EPITCH + c]           = acc[mt][nt][0] + bv0;
                st[r0w * EPITCH + c + 1]       = acc[mt][nt][1] + bv0;
                st[(r0w + 8) * EPITCH + c]     = acc[mt][nt][2] + bv1;
                st[(r0w + 8) * EPITCH + c + 1] = acc[mt][nt][3] + bv1;
            }
        }
    }
    __syncthreads();

    if (om == 0) {
        float* C = (float*)Cv + (size_t)b * sC;
        for (int i = tid; i < 128 * 16; i += 256) {
            const int r = i >> 4, q = (i & 15) << 2;
            float4 v = make_float4(st[r * EPITCH + q],     st[r * EPITCH + q + 1],
                                   st[r * EPITCH + q + 2], st[r * EPITCH + q + 3]);
            *(float4*)&C[(size_t)(m0out + r) * ldc + n0 + q] = v;
        }
    } else if (om == 1) {
        float* C = (float*)Cv + (size_t)b * sC;
        for (int i = tid; i < 64 * 32; i += 256) {
            const int n = i >> 5, mq = (i & 31) << 2;
            float4 v = make_float4(st[(mq + 0) * EPITCH + n], st[(mq + 1) * EPITCH + n],
                                   st[(mq + 2) * EPITCH + n], st[(mq + 3) * EPITCH + n]);
            *(float4*)&C[(size_t)(n0 + n) * ldc + m0out + mq] = v;
        }
    } else if (om == 3) {
        uint16_t* C = (uint16_t*)Cv + (size_t)b * sC;
        for (int i = tid; i < 128 * 16; i += 256) {
            const int r = i >> 4, q = (i & 15) << 2;
            const uint32_t h0 = packh2(st[r * EPITCH + q],     st[r * EPITCH + q + 1]);
            const uint32_t h1 = packh2(st[r * EPITCH + q + 2], st[r * EPITCH + q + 3]);
            *(uint2*)(C + (size_t)(m0out + r) * ldc + n0 + q) = make_uint2(h0, h1);
        }
    } else {
        // ---- om == 5: fused per-pixel channel softmax over the 128 staged rows ----
        // thread (c = pixel column 0..63, seg = 0..3 covering 32 rows each)
        uint16_t* C = (uint16_t*)C2v + (size_t)b * sC2;
        float* const redm = st + 128 * EPITCH;        // [4][64]
        float* const reds = redm + 256;               // [4][64]
        const int c = tid & 63, seg = tid >> 6;
        const int r0 = seg * 32;

        float m = -1e30f;
        #pragma unroll
        for (int r = 0; r < 32; ++r)
            m = fmaxf(m, st[(r0 + r) * EPITCH + c]);
        redm[seg * 64 + c] = m;
        __syncthreads();
        m = fmaxf(fmaxf(redm[c], redm[64 + c]), fmaxf(redm[128 + c], redm[192 + c]));

        float sum = 0.f;
        #pragma unroll
        for (int r = 0; r < 32; ++r) {
            const float e = __expf(st[(r0 + r) * EPITCH + c] - m);
            st[(r0 + r) * EPITCH + c] = e;
            sum += e;
        }
        reds[seg * 64 + c] = sum;
        __syncthreads();
        const float inv = 1.0f / (reds[c] + reds[64 + c] + reds[128 + c] + reds[192 + c]);

        // write 32 contiguous halves for pixel (n0+c), channels r0..r0+31
        uint2 buf[4];
        #pragma unroll
        for (int q = 0; q < 4; ++q) {
            const int r = q * 8;
            buf[q] = make_uint2(
                packh2(st[(r0 + r + 0) * EPITCH + c] * inv, st[(r0 + r + 1) * EPITCH + c] * inv),
                packh2(st[(r0 + r + 2) * EPITCH + c] * inv, st[(r0 + r + 3) * EPITCH + c] * inv));
            buf[q] = make_uint2(buf[q].x, buf[q].y);
            // second half of the 8-row group
            const uint2 b2 = make_uint2(
                packh2(st[(r0 + r + 4) * EPITCH + c] * inv, st[(r0 + r + 5) * EPITCH + c] * inv),
                packh2(st[(r0 + r + 6) * EPITCH + c] * inv, st[(r0 + r + 7) * EPITCH + c] * inv));
            uint16_t* dst = C + (size_t)(n0 + c) * ldc2 + r0 + r;
            *(uint2*)dst       = buf[q];
            *(uint2*)(dst + 4) = b2;
        }
    }
}

// ---------------------------------------------------------------------------
// Launch
// ---------------------------------------------------------------------------
extern "C" void kernel_launch(void* const* d_in, const int* in_sizes, int n_in,
                              void* d_out, int out_size)
{
    const float* x  = (const float*)d_in[0];
    const float* wA = (const float*)d_in[1];
    const float* bA = (const float*)d_in[2];
    const float* wB = (const float*)d_in[3];
    const float* bB = (const float*)d_in[4];
    const float* wV = (const float*)d_in[5];
    const float* bV = (const float*)d_in[6];
    float* out = (float*)d_out;

    __half *wAp, *wBVp, *xp, *aB, *aV, *xBT, *G;
    float *Bf, *bBV, *P;
    cudaGetSymbolAddress((void**)&wAp,  g_wA);
    cudaGetSymbolAddress((void**)&wBVp, g_wBV);
    cudaGetSymbolAddress((void**)&bBV,  g_bBV);
    cudaGetSymbolAddress((void**)&xp,   g_x);
    cudaGetSymbolAddress((void**)&Bf,   g_Bf);
    cudaGetSymbolAddress((void**)&aB,   g_aB);  cudaGetSymbolAddress((void**)&aV, g_aV);
    cudaGetSymbolAddress((void**)&P,    g_P);
    cudaGetSymbolAddress((void**)&xBT,  g_xBT);
    cudaGetSymbolAddress((void**)&G,    g_G);

    cudaFuncSetAttribute(k_mma, cudaFuncAttributeMaxDynamicSharedMemorySize, SMEM_BYTES);

    // ---- prep: one launch for all weights + bias; one for x ----
    k_prep<<<384, 256>>>((const float4*)wA, (const float4*)wB, (const float4*)wV,
                         bB, bV, (uint2*)wAp, (uint2*)wBVp, bBV);
    {
        const int n4 = NBATCH * CIN * HW / 4;
        k_cvt<<<(n4 + 255) / 256, 256>>>((const float4*)x, (uint2*)xp, n4);
    }

    // ---- K1: y=0 -> Bf = wB@x + bB (fp32); y=1 -> attV = softmax_c(wV@x + bV) fp16 ----
    k_mma<<<dim3(HW / 64, 2, NBATCH), 256, SMEM_BYTES>>>(
        wBVp, xp, Bf, aV, bBV,
        CIN, /*ldb=*/HW, /*ldc=*/HW, /*ldc2=*/CN, /*outmode=*/4, /*bmode=*/1,
        1, CIN,
        0, (long long)CIN * HW, (long long)CN * HW, (long long)HW * CN);

    // ---- attB: row softmax -> fp16 ----
    k_softmax_row<<<NBATCH * CN, 256>>>(Bf, aB);

    // ---- K4 (split-K x7): P[s] = x@attB^T slices -> fp32 trans partials ----
    k_mma<<<dim3(CN / 64, CIN / 128, NBATCH * KPARTS), 256, SMEM_BYTES>>>(
        xp, aB, P, nullptr, nullptr,
        HW, /*ldb=*/HW, /*ldc=*/CIN, 0, /*outmode=*/1, /*bmode=*/0,
        KPARTS, KSLICE,
        (long long)CIN * HW, (long long)CN * HW,
        (long long)CN * CIN, (long long)NBATCH * CN * CIN);

    // ---- reduce partials -> fp16 xBT ----
    {
        const int n4 = NBATCH * CN * CIN / 4;
        k_red<<<(n4 + 255) / 256, 256>>>((const float4*)P, (uint2*)xBT, n4);
    }

    // ---- K5: G = wA @ xB + bA -> fp16 normal ----
    k_mma<<<dim3(CN / 64, CM / 128, NBATCH), 256, SMEM_BYTES>>>(
        wAp, xBT, G, nullptr, bA,
        CIN, /*ldb=*/CIN, /*ldc=*/CN, 0, /*outmode=*/3, /*bmode=*/0,
        1, CIN,
        0, (long long)CN * CIN, (long long)CM * CN, 0);

    // ---- K6: Z[m][p] = sum_n G[m][n]*attV[p][n] -> fp32 out ----
    k_mma<<<dim3(HW / 64, CM / 128, NBATCH), 256, SMEM_BYTES>>>(
        G, aV, out, nullptr, nullptr,
        CN, /*ldb=*/CN, /*ldc=*/HW, 0, /*outmode=*/0, /*bmode=*/0,
        1, CN,
        (long long)CM * CN, (long long)HW * CN, (long long)CM * HW, 0);

    (void)in_sizes; (void)n_in; (void)out_size;
}